// round 1
// baseline (speedup 1.0000x reference)
#include <cuda_runtime.h>
#include <math.h>

#define NXc 128
#define NUc 64
#define NYc 32
#define KD  192
#define NO  160
#define EPSc 1e-4f
#define NS_ITERS 16
#define LAN_M 56

// ---------------- device scratch (static, no allocation) ----------------
__device__ float g_HtH[64 * 64];
__device__ float g_A0[NXc * NXc];
__device__ float g_A[NXc * NXc];
__device__ float g_B[NXc * NUc];
__device__ float g_C[NYc * NXc];
__device__ float g_Ybuf[2][NXc * NXc];
__device__ float g_Zbuf[2][NXc * NXc];
__device__ float g_T[NXc * NXc];
__device__ float g_W[KD * NO];
__device__ float g_scal[2];   // [0] = 1/||Q||_F ; [1] = sqrt(||Q||_F) / (1.01*sqrt(lam_max(HHt)))

// ---------------- phase 1: HtH = H^T H, A0 = -0.5(Q + G^T G + eps I) + S ----------------
__global__ void k_prep1(const float* __restrict__ Q, const float* __restrict__ S,
                        const float* __restrict__ G, const float* __restrict__ H) {
    int b = blockIdx.x, t = threadIdx.x;
    if (b < 16) {
        int e = b * 256 + t;
        int i = e >> 6, j = e & 63;
        float s = 0.f;
#pragma unroll 8
        for (int k = 0; k < 128; k++) s += H[k * 64 + i] * H[k * 64 + j];
        g_HtH[e] = s;
    } else {
        int e = (b - 16) * 256 + t;
        int i = e >> 7, j = e & 127;
        float s = 0.f;
#pragma unroll
        for (int k = 0; k < 32; k++) s += G[k * 128 + i] * G[k * 128 + j];
        float v = -0.5f * (Q[e] + s + ((i == j) ? EPSc : 0.f)) + S[e];
        g_A0[e] = v;
    }
}

// ---------------- phase 2: Frobenius(Q) + Lanczos lambda_max(HtH), single CTA ----------------
__global__ void k_spec(const float* __restrict__ Qm) {
    __shared__ float sM[64 * 64];
    __shared__ float v[64], vp[64];
    __shared__ float red[64];
    __shared__ float al[LAN_M], be[LAN_M + 1];
    int t = threadIdx.x;

    for (int i = t; i < 4096; i += 64) sM[i] = g_HtH[i];

    // Frobenius norm of Q
    float s = 0.f;
    for (int i = t; i < 16384; i += 64) { float q = Qm[i]; s += q * q; }
    red[t] = s; __syncthreads();
    for (int off = 32; off > 0; off >>= 1) { if (t < off) red[t] += red[t + off]; __syncthreads(); }
    float cfro = sqrtf(red[0]);
    __syncthreads();

    // v0 = normalize(M * ones)
    float rs = 0.f;
    for (int k = 0; k < 64; k++) rs += sM[t * 64 + k];
    red[t] = rs * rs; __syncthreads();
    for (int off = 32; off > 0; off >>= 1) { if (t < off) red[t] += red[t + off]; __syncthreads(); }
    float n0 = sqrtf(red[0]); __syncthreads();
    v[t] = rs / n0;
    vp[t] = 0.f;
    if (t == 0) be[0] = 0.f;
    __syncthreads();

    for (int j = 0; j < LAN_M; j++) {
        float acc = 0.f;
#pragma unroll 8
        for (int k = 0; k < 64; k++) acc += sM[t * 64 + k] * v[k];
        float wi = acc - be[j] * vp[t];

        red[t] = wi * v[t]; __syncthreads();
        for (int off = 32; off > 0; off >>= 1) { if (t < off) red[t] += red[t + off]; __syncthreads(); }
        float a = red[0]; __syncthreads();
        if (t == 0) al[j] = a;
        wi -= a * v[t];

        red[t] = wi * wi; __syncthreads();
        for (int off = 32; off > 0; off >>= 1) { if (t < off) red[t] += red[t + off]; __syncthreads(); }
        float bn = sqrtf(red[0]); __syncthreads();
        if (t == 0) be[j + 1] = bn;

        vp[t] = v[t];
        v[t] = (bn > 1e-12f) ? (wi / bn) : 0.f;
        __syncthreads();
    }

    if (t == 0) {
        // bisection (Sturm) for lambda_max of tridiagonal T
        double hi = 0.0, lo = 0.0;
        for (int j = 0; j < LAN_M; j++) {
            double g = (double)al[j] + fabs((double)be[j]) + fabs((double)be[j + 1]);
            if (g > hi) hi = g;
        }
        hi += 1.0;
        for (int it = 0; it < 64; ++it) {
            double xm = 0.5 * (lo + hi);
            int cnt = 0; double d = 1.0;
            for (int j = 0; j < LAN_M; j++) {
                double bj = (j == 0) ? 0.0 : (double)be[j];
                d = ((double)al[j] - xm) - bj * bj / d;
                if (d == 0.0) d = -1e-30;
                if (d < 0.0) cnt++;
            }
            if (cnt >= LAN_M) hi = xm; else lo = xm;
        }
        double lam = 0.5 * (lo + hi);
        if (lam < 1e-20) lam = 1e-20;
        g_scal[0] = 1.0f / cfro;
        g_scal[1] = (float)(sqrt((double)cfro) / (1.01 * sqrt(lam)));
    }
}

// ---------------- phase 3: A = A0 @ P ; C = G @ P ; Y0 = Q/c ; Z0 = I ----------------
__global__ void k_init(const float* __restrict__ P, const float* __restrict__ G,
                       const float* __restrict__ Qm) {
    int b = blockIdx.x, t = threadIdx.x;
    if (b < 64) {
        int e = b * 256 + t;
        int i = e >> 7, j = e & 127;
        const float* a0 = &g_A0[i * 128];
        float s = 0.f;
#pragma unroll 8
        for (int k = 0; k < 128; k++) s += a0[k] * P[k * 128 + j];
        g_A[e] = s;
    } else if (b < 80) {
        int e = (b - 64) * 256 + t;
        int i = e >> 7, j = e & 127;
        const float* gi = &G[i * 128];
        float s = 0.f;
#pragma unroll 8
        for (int k = 0; k < 128; k++) s += gi[k] * P[k * 128 + j];
        g_C[e] = s;
    } else {
        float ic = g_scal[0];
        int base = (b - 80) * 1024 + t;
#pragma unroll
        for (int r = 0; r < 4; r++) {
            int idx = base + r * 256;
            if (idx < 16384) {
                g_Ybuf[0][idx] = Qm[idx] * ic;
            } else {
                int e2 = idx - 16384;
                g_Zbuf[0][e2] = ((e2 >> 7) == (e2 & 127)) ? 1.f : 0.f;
            }
        }
    }
}

// ---------------- Newton-Schulz: T = 1.5 I - 0.5 Z@Y ----------------
__global__ void k_ns_T(int p) {
    const float* Zc = g_Zbuf[p];
    const float* Yc = g_Ybuf[p];
    int e = blockIdx.x * 256 + threadIdx.x;
    int i = e >> 7, j = e & 127;
    const float* zr = &Zc[i * 128];
    float s = 0.f;
#pragma unroll 8
    for (int k = 0; k < 128; k++) s += zr[k] * Yc[k * 128 + j];
    g_T[e] = ((i == j) ? 1.5f : 0.f) - 0.5f * s;
}

// ---------------- Newton-Schulz: Ynew = Y@T ; Znew = T@Z ----------------
__global__ void k_ns_YZ(int p) {
    const float* Yc = g_Ybuf[p];
    const float* Zc = g_Zbuf[p];
    float* Yn = g_Ybuf[p ^ 1];
    float* Zn = g_Zbuf[p ^ 1];
    int b = blockIdx.x, t = threadIdx.x;
    if (b < 64) {
        int e = b * 256 + t;
        int i = e >> 7, j = e & 127;
        const float* yr = &Yc[i * 128];
        float s = 0.f;
#pragma unroll 8
        for (int k = 0; k < 128; k++) s += yr[k] * g_T[k * 128 + j];
        Yn[e] = s;
    } else {
        int e = (b - 64) * 256 + t;
        int i = e >> 7, j = e & 127;
        const float* tr = &g_T[i * 128];
        float s = 0.f;
#pragma unroll 8
        for (int k = 0; k < 128; k++) s += tr[k] * Zc[k * 128 + j];
        Zn[e] = s;
    }
}

// ---------------- B = (sqrt(c)/denom) * Yfinal @ H ----------------
__global__ void k_B(int p, const float* __restrict__ H) {
    const float* Yf = g_Ybuf[p];
    int e = blockIdx.x * 256 + threadIdx.x;
    int i = e >> 6, j = e & 63;
    const float* yr = &Yf[i * 128];
    float s = 0.f;
#pragma unroll 8
    for (int k = 0; k < 128; k++) s += yr[k] * H[k * 64 + j];
    g_B[e] = s * g_scal[1];
}

// ---------------- pack W[k][o]: o<128 -> A[o][k]/B[o][k-128], o>=128 -> C[o-128][k] ----------------
__global__ void k_pack() {
    int idx = blockIdx.x * 256 + threadIdx.x;
    int k = idx / NO, o = idx % NO;
    float v;
    if (k < 128) v = (o < 128) ? g_A[o * 128 + k] : g_C[(o - 128) * 128 + k];
    else         v = (o < 128) ? g_B[o * 64 + (k - 128)] : 0.f;
    g_W[idx] = v;
}

// ---------------- main batched GEMM: block = 128 samples x 160 outputs, K=192 ----------------
__global__ void __launch_bounds__(256, 1) k_main(
    const float* __restrict__ x, const float* __restrict__ u,
    float* __restrict__ dx, float* __restrict__ y) {
    extern __shared__ float sm[];
    float* sW = sm;               // KD*NO = 30720 floats
    float* sZ = sm + KD * NO;     // 16*128 = 2048 floats, layout sZ[k][sample]

    int t = threadIdx.x;
    int to = t & 15;              // output group (16 groups)
    int ts = t >> 4;              // sample group (16 groups)
    int blockBase = blockIdx.x * 128;

    for (int i = t; i < KD * NO; i += 256) sW[i] = g_W[i];

    float acc[8][8];
    float accy[8][2];
#pragma unroll
    for (int i = 0; i < 8; i++) {
        accy[i][0] = accy[i][1] = 0.f;
#pragma unroll
        for (int j = 0; j < 8; j++) acc[i][j] = 0.f;
    }

    int q0 = t * 2;               // this thread's 2 float4 chunks of the 512-float4 stage
    int samp0 = q0 >> 2,       c40 = q0 & 3;
    int samp1 = (q0 + 1) >> 2, c41 = (q0 + 1) & 3;

    float4 pf0, pf1;
    // prologue: stage 0 comes from x, k-offset 0
    pf0 = *(const float4*)&x[(size_t)(blockBase + samp0) * 128 + c40 * 4];
    pf1 = *(const float4*)&x[(size_t)(blockBase + samp1) * 128 + c41 * 4];

    for (int st = 0; st < 12; ++st) {
        __syncthreads();
        // store prefetched stage (transposed: sZ[k][sample])
        sZ[(c40 * 4 + 0) * 128 + samp0] = pf0.x;
        sZ[(c40 * 4 + 1) * 128 + samp0] = pf0.y;
        sZ[(c40 * 4 + 2) * 128 + samp0] = pf0.z;
        sZ[(c40 * 4 + 3) * 128 + samp0] = pf0.w;
        sZ[(c41 * 4 + 0) * 128 + samp1] = pf1.x;
        sZ[(c41 * 4 + 1) * 128 + samp1] = pf1.y;
        sZ[(c41 * 4 + 2) * 128 + samp1] = pf1.z;
        sZ[(c41 * 4 + 3) * 128 + samp1] = pf1.w;

        // prefetch next stage
        if (st + 1 < 12) {
            int ns = st + 1;
            if (ns < 8) {
                pf0 = *(const float4*)&x[(size_t)(blockBase + samp0) * 128 + ns * 16 + c40 * 4];
                pf1 = *(const float4*)&x[(size_t)(blockBase + samp1) * 128 + ns * 16 + c41 * 4];
            } else {
                int ko = (ns - 8) * 16;
                pf0 = *(const float4*)&u[(size_t)(blockBase + samp0) * 64 + ko + c40 * 4];
                pf1 = *(const float4*)&u[(size_t)(blockBase + samp1) * 64 + ko + c41 * 4];
            }
        }
        __syncthreads();

        const float* wbase = &sW[st * 16 * NO];
#pragma unroll 4
        for (int kk = 0; kk < 16; kk++) {
            const float* wr = wbase + kk * NO;
            float4 w0 = *(const float4*)&wr[to * 8];
            float4 w1 = *(const float4*)&wr[to * 8 + 4];
            float2 wy = *(const float2*)&wr[128 + to * 2];
            float4 z0 = *(const float4*)&sZ[kk * 128 + ts * 8];
            float4 z1 = *(const float4*)&sZ[kk * 128 + ts * 8 + 4];
            float zz[8] = {z0.x, z0.y, z0.z, z0.w, z1.x, z1.y, z1.z, z1.w};
            float ww[8] = {w0.x, w0.y, w0.z, w0.w, w1.x, w1.y, w1.z, w1.w};
#pragma unroll
            for (int i = 0; i < 8; i++) {
#pragma unroll
                for (int j = 0; j < 8; j++) acc[i][j] += zz[i] * ww[j];
                accy[i][0] += zz[i] * wy.x;
                accy[i][1] += zz[i] * wy.y;
            }
        }
    }

    // epilogue
#pragma unroll
    for (int i = 0; i < 8; i++) {
        size_t s = (size_t)blockBase + ts * 8 + i;
        float4 o0 = make_float4(acc[i][0], acc[i][1], acc[i][2], acc[i][3]);
        float4 o1 = make_float4(acc[i][4], acc[i][5], acc[i][6], acc[i][7]);
        *(float4*)&dx[s * 128 + to * 8]     = o0;
        *(float4*)&dx[s * 128 + to * 8 + 4] = o1;
        float2 oy = make_float2(accy[i][0], accy[i][1]);
        *(float2*)&y[s * 32 + to * 2] = oy;
    }
}

// ---------------- launcher ----------------
extern "C" void kernel_launch(void* const* d_in, const int* in_sizes, int n_in,
                              void* d_out, int out_size) {
    const float* u = (const float*)d_in[0];
    const float* x = (const float*)d_in[1];
    const float* Q = (const float*)d_in[2];
    const float* P = (const float*)d_in[3];
    const float* S = (const float*)d_in[4];
    const float* G = (const float*)d_in[5];
    const float* H = (const float*)d_in[6];
    int N = in_sizes[0] / 64;     // u is (N, 64)

    float* dx = (float*)d_out;
    float* y  = dx + (size_t)N * 128;

    // setup phase
    k_prep1<<<80, 256>>>(Q, S, G, H);
    k_spec<<<1, 64>>>(Q);
    k_init<<<112, 256>>>(P, G, Q);

    int p = 0;
    for (int it = 0; it < NS_ITERS; ++it) {
        k_ns_T<<<64, 256>>>(p);
        k_ns_YZ<<<128, 256>>>(p);
        p ^= 1;
    }
    k_B<<<32, 256>>>(p, H);
    k_pack<<<120, 256>>>();

    // main GEMM
    int smem = (KD * NO + 16 * 128) * sizeof(float);   // 131072 bytes
    cudaFuncSetAttribute(k_main, cudaFuncAttributeMaxDynamicSharedMemorySize, smem);
    int blocks = N / 128;
    k_main<<<blocks, 256, smem>>>(x, u, dx, y);
}

// round 2
// speedup vs baseline: 1.0004x; 1.0004x over previous
#include <cuda_runtime.h>
#include <math.h>

#define NXc 128
#define NUc 64
#define NYc 32
#define KD  192
#define NO  160
#define EPSc 1e-4f
#define NS_ITERS 16
#define LAN_M 56

// ---------------- device scratch (static, no allocation) ----------------
__device__ float g_HtH[64 * 64];
__device__ float g_A0[NXc * NXc];
__device__ float g_A[NXc * NXc];
__device__ float g_B[NXc * NUc];
__device__ float g_C[NYc * NXc];
__device__ float g_Ybuf[2][NXc * NXc];
__device__ float g_Zbuf[2][NXc * NXc];
__device__ float g_T[NXc * NXc];
__device__ float g_W[KD * NO];
__device__ float g_scal[2];   // [0] = 1/||Q||_F ; [1] = sqrt(||Q||_F) / (1.01*sqrt(lam_max(HHt)))

// ---------------- phase 1: HtH = H^T H, A0 = -0.5(Q + G^T G + eps I) + S ----------------
__global__ void k_prep1(const float* __restrict__ Q, const float* __restrict__ S,
                        const float* __restrict__ G, const float* __restrict__ H) {
    int b = blockIdx.x, t = threadIdx.x;
    if (b < 16) {
        int e = b * 256 + t;
        int i = e >> 6, j = e & 63;
        float s = 0.f;
#pragma unroll 8
        for (int k = 0; k < 128; k++) s += H[k * 64 + i] * H[k * 64 + j];
        g_HtH[e] = s;
    } else {
        int e = (b - 16) * 256 + t;
        int i = e >> 7, j = e & 127;
        float s = 0.f;
#pragma unroll
        for (int k = 0; k < 32; k++) s += G[k * 128 + i] * G[k * 128 + j];
        float v = -0.5f * (Q[e] + s + ((i == j) ? EPSc : 0.f)) + S[e];
        g_A0[e] = v;
    }
}

// ---------------- phase 2: Frobenius(Q) + Lanczos lambda_max(HtH), single CTA ----------------
__global__ void k_spec(const float* __restrict__ Qm) {
    __shared__ float sM[64 * 64];
    __shared__ float v[64], vp[64];
    __shared__ float red[64];
    __shared__ float al[LAN_M], be[LAN_M + 1];
    int t = threadIdx.x;

    for (int i = t; i < 4096; i += 64) sM[i] = g_HtH[i];

    // Frobenius norm of Q
    float s = 0.f;
    for (int i = t; i < 16384; i += 64) { float q = Qm[i]; s += q * q; }
    red[t] = s; __syncthreads();
    for (int off = 32; off > 0; off >>= 1) { if (t < off) red[t] += red[t + off]; __syncthreads(); }
    float cfro = sqrtf(red[0]);
    __syncthreads();

    // v0 = normalize(M * ones)
    float rs = 0.f;
    for (int k = 0; k < 64; k++) rs += sM[t * 64 + k];
    red[t] = rs * rs; __syncthreads();
    for (int off = 32; off > 0; off >>= 1) { if (t < off) red[t] += red[t + off]; __syncthreads(); }
    float n0 = sqrtf(red[0]); __syncthreads();
    v[t] = rs / n0;
    vp[t] = 0.f;
    if (t == 0) be[0] = 0.f;
    __syncthreads();

    for (int j = 0; j < LAN_M; j++) {
        float acc = 0.f;
#pragma unroll 8
        for (int k = 0; k < 64; k++) acc += sM[t * 64 + k] * v[k];
        float wi = acc - be[j] * vp[t];

        red[t] = wi * v[t]; __syncthreads();
        for (int off = 32; off > 0; off >>= 1) { if (t < off) red[t] += red[t + off]; __syncthreads(); }
        float a = red[0]; __syncthreads();
        if (t == 0) al[j] = a;
        wi -= a * v[t];

        red[t] = wi * wi; __syncthreads();
        for (int off = 32; off > 0; off >>= 1) { if (t < off) red[t] += red[t + off]; __syncthreads(); }
        float bn = sqrtf(red[0]); __syncthreads();
        if (t == 0) be[j + 1] = bn;

        vp[t] = v[t];
        v[t] = (bn > 1e-12f) ? (wi / bn) : 0.f;
        __syncthreads();
    }

    if (t == 0) {
        // bisection (Sturm) for lambda_max of tridiagonal T
        double hi = 0.0, lo = 0.0;
        for (int j = 0; j < LAN_M; j++) {
            double g = (double)al[j] + fabs((double)be[j]) + fabs((double)be[j + 1]);
            if (g > hi) hi = g;
        }
        hi += 1.0;
        for (int it = 0; it < 64; ++it) {
            double xm = 0.5 * (lo + hi);
            int cnt = 0; double d = 1.0;
            for (int j = 0; j < LAN_M; j++) {
                double bj = (j == 0) ? 0.0 : (double)be[j];
                d = ((double)al[j] - xm) - bj * bj / d;
                if (d == 0.0) d = -1e-30;
                if (d < 0.0) cnt++;
            }
            if (cnt >= LAN_M) hi = xm; else lo = xm;
        }
        double lam = 0.5 * (lo + hi);
        if (lam < 1e-20) lam = 1e-20;
        g_scal[0] = 1.0f / cfro;
        g_scal[1] = (float)(sqrt((double)cfro) / (1.01 * sqrt(lam)));
    }
}

// ---------------- phase 3: A = A0 @ P ; C = G @ P ; Y0 = Q/c ; Z0 = I ----------------
__global__ void k_init(const float* __restrict__ P, const float* __restrict__ G,
                       const float* __restrict__ Qm) {
    int b = blockIdx.x, t = threadIdx.x;
    if (b < 64) {
        int e = b * 256 + t;
        int i = e >> 7, j = e & 127;
        const float* a0 = &g_A0[i * 128];
        float s = 0.f;
#pragma unroll 8
        for (int k = 0; k < 128; k++) s += a0[k] * P[k * 128 + j];
        g_A[e] = s;
    } else if (b < 80) {
        int e = (b - 64) * 256 + t;
        int i = e >> 7, j = e & 127;
        const float* gi = &G[i * 128];
        float s = 0.f;
#pragma unroll 8
        for (int k = 0; k < 128; k++) s += gi[k] * P[k * 128 + j];
        g_C[e] = s;
    } else {
        float ic = g_scal[0];
        int base = (b - 80) * 1024 + t;
#pragma unroll
        for (int r = 0; r < 4; r++) {
            int idx = base + r * 256;
            if (idx < 16384) {
                g_Ybuf[0][idx] = Qm[idx] * ic;
            } else {
                int e2 = idx - 16384;
                g_Zbuf[0][e2] = ((e2 >> 7) == (e2 & 127)) ? 1.f : 0.f;
            }
        }
    }
}

// ---------------- Newton-Schulz: T = 1.5 I - 0.5 Z@Y ----------------
__global__ void k_ns_T(int p) {
    const float* Zc = g_Zbuf[p];
    const float* Yc = g_Ybuf[p];
    int e = blockIdx.x * 256 + threadIdx.x;
    int i = e >> 7, j = e & 127;
    const float* zr = &Zc[i * 128];
    float s = 0.f;
#pragma unroll 8
    for (int k = 0; k < 128; k++) s += zr[k] * Yc[k * 128 + j];
    g_T[e] = ((i == j) ? 1.5f : 0.f) - 0.5f * s;
}

// ---------------- Newton-Schulz: Ynew = Y@T ; Znew = T@Z ----------------
__global__ void k_ns_YZ(int p) {
    const float* Yc = g_Ybuf[p];
    const float* Zc = g_Zbuf[p];
    float* Yn = g_Ybuf[p ^ 1];
    float* Zn = g_Zbuf[p ^ 1];
    int b = blockIdx.x, t = threadIdx.x;
    if (b < 64) {
        int e = b * 256 + t;
        int i = e >> 7, j = e & 127;
        const float* yr = &Yc[i * 128];
        float s = 0.f;
#pragma unroll 8
        for (int k = 0; k < 128; k++) s += yr[k] * g_T[k * 128 + j];
        Yn[e] = s;
    } else {
        int e = (b - 64) * 256 + t;
        int i = e >> 7, j = e & 127;
        const float* tr = &g_T[i * 128];
        float s = 0.f;
#pragma unroll 8
        for (int k = 0; k < 128; k++) s += tr[k] * Zc[k * 128 + j];
        Zn[e] = s;
    }
}

// ---------------- B = (sqrt(c)/denom) * Yfinal @ H ----------------
__global__ void k_B(int p, const float* __restrict__ H) {
    const float* Yf = g_Ybuf[p];
    int e = blockIdx.x * 256 + threadIdx.x;
    int i = e >> 6, j = e & 63;
    const float* yr = &Yf[i * 128];
    float s = 0.f;
#pragma unroll 8
    for (int k = 0; k < 128; k++) s += yr[k] * H[k * 64 + j];
    g_B[e] = s * g_scal[1];
}

// ---------------- pack W[k][o]: o<128 -> A[o][k]/B[o][k-128], o>=128 -> C[o-128][k] ----------------
__global__ void k_pack() {
    int idx = blockIdx.x * 256 + threadIdx.x;
    int k = idx / NO, o = idx % NO;
    float v;
    if (k < 128) v = (o < 128) ? g_A[o * 128 + k] : g_C[(o - 128) * 128 + k];
    else         v = (o < 128) ? g_B[o * 64 + (k - 128)] : 0.f;
    g_W[idx] = v;
}

// ---------------- main batched GEMM: block = 128 samples x 160 outputs, K=192 ----------------
__global__ void __launch_bounds__(256, 1) k_main(
    const float* __restrict__ x, const float* __restrict__ u,
    float* __restrict__ dx, float* __restrict__ y) {
    extern __shared__ float sm[];
    float* sW = sm;               // KD*NO = 30720 floats
    float* sZ = sm + KD * NO;     // 16*128 = 2048 floats, layout sZ[k][sample]

    int t = threadIdx.x;
    int to = t & 15;              // output group (16 groups)
    int ts = t >> 4;              // sample group (16 groups)
    int blockBase = blockIdx.x * 128;

    for (int i = t; i < KD * NO; i += 256) sW[i] = g_W[i];

    float acc[8][8];
    float accy[8][2];
#pragma unroll
    for (int i = 0; i < 8; i++) {
        accy[i][0] = accy[i][1] = 0.f;
#pragma unroll
        for (int j = 0; j < 8; j++) acc[i][j] = 0.f;
    }

    int q0 = t * 2;               // this thread's 2 float4 chunks of the 512-float4 stage
    int samp0 = q0 >> 2,       c40 = q0 & 3;
    int samp1 = (q0 + 1) >> 2, c41 = (q0 + 1) & 3;

    float4 pf0, pf1;
    // prologue: stage 0 comes from x, k-offset 0
    pf0 = *(const float4*)&x[(size_t)(blockBase + samp0) * 128 + c40 * 4];
    pf1 = *(const float4*)&x[(size_t)(blockBase + samp1) * 128 + c41 * 4];

    for (int st = 0; st < 12; ++st) {
        __syncthreads();
        // store prefetched stage (transposed: sZ[k][sample])
        sZ[(c40 * 4 + 0) * 128 + samp0] = pf0.x;
        sZ[(c40 * 4 + 1) * 128 + samp0] = pf0.y;
        sZ[(c40 * 4 + 2) * 128 + samp0] = pf0.z;
        sZ[(c40 * 4 + 3) * 128 + samp0] = pf0.w;
        sZ[(c41 * 4 + 0) * 128 + samp1] = pf1.x;
        sZ[(c41 * 4 + 1) * 128 + samp1] = pf1.y;
        sZ[(c41 * 4 + 2) * 128 + samp1] = pf1.z;
        sZ[(c41 * 4 + 3) * 128 + samp1] = pf1.w;

        // prefetch next stage
        if (st + 1 < 12) {
            int ns = st + 1;
            if (ns < 8) {
                pf0 = *(const float4*)&x[(size_t)(blockBase + samp0) * 128 + ns * 16 + c40 * 4];
                pf1 = *(const float4*)&x[(size_t)(blockBase + samp1) * 128 + ns * 16 + c41 * 4];
            } else {
                int ko = (ns - 8) * 16;
                pf0 = *(const float4*)&u[(size_t)(blockBase + samp0) * 64 + ko + c40 * 4];
                pf1 = *(const float4*)&u[(size_t)(blockBase + samp1) * 64 + ko + c41 * 4];
            }
        }
        __syncthreads();

        const float* wbase = &sW[st * 16 * NO];
#pragma unroll 4
        for (int kk = 0; kk < 16; kk++) {
            const float* wr = wbase + kk * NO;
            float4 w0 = *(const float4*)&wr[to * 8];
            float4 w1 = *(const float4*)&wr[to * 8 + 4];
            float2 wy = *(const float2*)&wr[128 + to * 2];
            float4 z0 = *(const float4*)&sZ[kk * 128 + ts * 8];
            float4 z1 = *(const float4*)&sZ[kk * 128 + ts * 8 + 4];
            float zz[8] = {z0.x, z0.y, z0.z, z0.w, z1.x, z1.y, z1.z, z1.w};
            float ww[8] = {w0.x, w0.y, w0.z, w0.w, w1.x, w1.y, w1.z, w1.w};
#pragma unroll
            for (int i = 0; i < 8; i++) {
#pragma unroll
                for (int j = 0; j < 8; j++) acc[i][j] += zz[i] * ww[j];
                accy[i][0] += zz[i] * wy.x;
                accy[i][1] += zz[i] * wy.y;
            }
        }
    }

    // epilogue
#pragma unroll
    for (int i = 0; i < 8; i++) {
        size_t s = (size_t)blockBase + ts * 8 + i;
        float4 o0 = make_float4(acc[i][0], acc[i][1], acc[i][2], acc[i][3]);
        float4 o1 = make_float4(acc[i][4], acc[i][5], acc[i][6], acc[i][7]);
        *(float4*)&dx[s * 128 + to * 8]     = o0;
        *(float4*)&dx[s * 128 + to * 8 + 4] = o1;
        float2 oy = make_float2(accy[i][0], accy[i][1]);
        *(float2*)&y[s * 32 + to * 2] = oy;
    }
}

// ---------------- launcher ----------------
extern "C" void kernel_launch(void* const* d_in, const int* in_sizes, int n_in,
                              void* d_out, int out_size) {
    const float* u = (const float*)d_in[0];
    const float* x = (const float*)d_in[1];
    const float* Q = (const float*)d_in[2];
    const float* P = (const float*)d_in[3];
    const float* S = (const float*)d_in[4];
    const float* G = (const float*)d_in[5];
    const float* H = (const float*)d_in[6];
    int N = in_sizes[0] / 64;     // u is (N, 64)

    float* dx = (float*)d_out;
    float* y  = dx + (size_t)N * 128;

    // setup phase
    k_prep1<<<80, 256>>>(Q, S, G, H);
    k_spec<<<1, 64>>>(Q);
    k_init<<<112, 256>>>(P, G, Q);

    int p = 0;
    for (int it = 0; it < NS_ITERS; ++it) {
        k_ns_T<<<64, 256>>>(p);
        k_ns_YZ<<<128, 256>>>(p);
        p ^= 1;
    }
    k_B<<<32, 256>>>(p, H);
    k_pack<<<120, 256>>>();

    // main GEMM
    int smem = (KD * NO + 16 * 128) * sizeof(float);   // 131072 bytes
    cudaFuncSetAttribute(k_main, cudaFuncAttributeMaxDynamicSharedMemorySize, smem);
    int blocks = N / 128;
    k_main<<<blocks, 256, smem>>>(x, u, dx, y);
}

// round 5
// speedup vs baseline: 1.2002x; 1.1998x over previous
#include <cuda_runtime.h>
#include <cuda_bf16.h>
#include <math.h>
#include <stdint.h>

#define NS_ITERS 16
#define LAN_M 56
#define EPSc 1e-4f
#define NSGRID 128
#define IDESC_MAIN 0x8280490u   // f32 accum, bf16 a/b, M=128, N=160
#define W_IMG_HALF 61440
#define W_IMG_BYTES 122880

// tcgen05 only exists on arch-specific targets (sm_103a). The harness also
// runs a generic compute_103 PTX pass, which must compile a fallback.
#if !defined(__CUDA_ARCH__) || defined(__CUDA_ARCH_FEAT_SM103_ALL) || defined(__CUDA_ARCH_FEAT_SM100_ALL)
#define TC_OK 1
#else
#define TC_OK 0
#endif

// ---------------- PTX helpers ----------------
__device__ __forceinline__ uint32_t smem_u32(const void* p) {
    uint32_t a;
    asm("{ .reg .u64 t; cvta.to.shared.u64 t, %1; cvt.u32.u64 %0, t; }" : "=r"(a) : "l"(p));
    return a;
}
__device__ __forceinline__ uint32_t elect_one_pred() {
    uint32_t pred;
    asm volatile("{\n\t.reg .pred p;\n\telect.sync _|p, 0xFFFFFFFF;\n\tselp.b32 %0, 1, 0, p;\n\t}" : "=r"(pred));
    return pred;
}
#define TCGEN05_ALLOC(a, n) asm volatile("tcgen05.alloc.cta_group::1.sync.aligned.shared::cta.b32 [%0], %1;" :: "r"((uint32_t)(a)), "r"((uint32_t)(n)) : "memory")
#define TCGEN05_DEALLOC(a, n) asm volatile("tcgen05.dealloc.cta_group::1.sync.aligned.b32 %0, %1;" :: "r"(a), "r"((uint32_t)(n)))
#define TCGEN05_RELINQ() asm volatile("tcgen05.relinquish_alloc_permit.cta_group::1.sync.aligned;")
#define TCGEN05_WAIT_ST() asm volatile("tcgen05.wait::st.sync.aligned;" ::: "memory")
#define TCGEN05_WAIT_LD() asm volatile("tcgen05.wait::ld.sync.aligned;" ::: "memory")
#define TCGEN05_FENCE_BEFORE() asm volatile("tcgen05.fence::before_thread_sync;" ::: "memory")
#define TCGEN05_FENCE_AFTER()  asm volatile("tcgen05.fence::after_thread_sync;" ::: "memory")
#define TCGEN05_COMMIT(m) asm volatile("tcgen05.commit.cta_group::1.mbarrier::arrive::one.shared::cluster.b64 [%0];" :: "r"((uint32_t)(m)) : "memory")
#define MBARRIER_INIT(m, c) asm volatile("mbarrier.init.shared.b64 [%0], %1;" :: "r"((uint32_t)(m)), "r"((uint32_t)(c)) : "memory")
#define MBARRIER_WAIT_PARITY(m, ph) do { \
    uint32_t _m = (uint32_t)(m), _p = (uint32_t)(ph), _d; \
    asm volatile("{\n\t.reg .pred p;\n\tmbarrier.try_wait.parity.acquire.cta.shared::cta.b64 p, [%1], %2;\n\tselp.b32 %0, 1, 0, p;\n\t}" : "=r"(_d) : "r"(_m), "r"(_p) : "memory"); \
    if (!_d) { asm volatile("{\n\t.reg .pred P1;\n\tWL_%=:\n\tmbarrier.try_wait.parity.acquire.cta.shared::cta.b64 P1, [%0], %1, 0x989680;\n\t@P1 bra.uni WD_%=;\n\tbra.uni WL_%=;\n\tWD_%=:\n\t}" :: "r"(_m), "r"(_p) : "memory"); } \
} while (0)
#define TCGEN05_MMA_F16(d, a, bd, id, en) do { \
    uint32_t _e = (en) ? 1 : 0, _z = 0; \
    asm volatile("{\n\t.reg .pred p;\n\tsetp.ne.u32 p, %6, 0;\n\ttcgen05.mma.cta_group::1.kind::f16 [%0], [%1], %2, %3, {%4, %4, %4, %4}, p;\n\t}" \
        :: "r"(d), "r"(a), "l"(bd), "r"(id), "r"(_z), "r"(_z), "r"(_e) : "memory"); \
} while (0)
#define TCGEN05_ST_X16(a, r) asm volatile("tcgen05.st.sync.aligned.32x32b.x16.b32 [%0], {%1,%2,%3,%4,%5,%6,%7,%8,%9,%10,%11,%12,%13,%14,%15,%16};" \
    :: "r"(a), "r"((r)[0]), "r"((r)[1]), "r"((r)[2]), "r"((r)[3]), "r"((r)[4]), "r"((r)[5]), "r"((r)[6]), "r"((r)[7]), \
       "r"((r)[8]), "r"((r)[9]), "r"((r)[10]), "r"((r)[11]), "r"((r)[12]), "r"((r)[13]), "r"((r)[14]), "r"((r)[15]) : "memory")
#define TCGEN05_LD_X32(r, a) asm volatile("tcgen05.ld.sync.aligned.32x32b.x32.b32 {%0,%1,%2,%3,%4,%5,%6,%7,%8,%9,%10,%11,%12,%13,%14,%15,%16,%17,%18,%19,%20,%21,%22,%23,%24,%25,%26,%27,%28,%29,%30,%31}, [%32];" \
    : "=r"((r)[0]), "=r"((r)[1]), "=r"((r)[2]), "=r"((r)[3]), "=r"((r)[4]), "=r"((r)[5]), "=r"((r)[6]), "=r"((r)[7]), \
      "=r"((r)[8]), "=r"((r)[9]), "=r"((r)[10]), "=r"((r)[11]), "=r"((r)[12]), "=r"((r)[13]), "=r"((r)[14]), "=r"((r)[15]), \
      "=r"((r)[16]), "=r"((r)[17]), "=r"((r)[18]), "=r"((r)[19]), "=r"((r)[20]), "=r"((r)[21]), "=r"((r)[22]), "=r"((r)[23]), \
      "=r"((r)[24]), "=r"((r)[25]), "=r"((r)[26]), "=r"((r)[27]), "=r"((r)[28]), "=r"((r)[29]), "=r"((r)[30]), "=r"((r)[31]) : "r"(a))
static __device__ __forceinline__ uint64_t make_desc(uint32_t addr) {
    return ((uint64_t)2 << 61) | ((uint64_t)1 << 46) | ((uint64_t)64 << 32) | ((uint64_t)1 << 16)
         | ((uint64_t)(addr >> 4) & 0x3FFF);
}

// ---------------- device scratch ----------------
__device__ float g_HtH[64 * 64];
__device__ float g_A0[128 * 128];
__device__ float g_A[128 * 128];
__device__ float g_B[128 * 64];
__device__ float g_C[32 * 128];
__device__ float g_Ybuf[2][128 * 128];
__device__ float g_Zbuf[2][128 * 128];
__device__ float g_T[128 * 128];
__device__ float g_scal[2];
__device__ unsigned g_cnt;
__device__ __align__(16) unsigned char g_Wimg[W_IMG_BYTES];

// ---------------- setup: HtH + A0 ----------------
__global__ void k_prep1(const float* __restrict__ Q, const float* __restrict__ S,
                        const float* __restrict__ G, const float* __restrict__ H) {
    int b = blockIdx.x, t = threadIdx.x;
    if (b < 16) {
        int e = b * 256 + t, i = e >> 6, j = e & 63;
        float s = 0.f;
#pragma unroll 8
        for (int k = 0; k < 128; k++) s += H[k * 64 + i] * H[k * 64 + j];
        g_HtH[e] = s;
    } else {
        int e = (b - 16) * 256 + t, i = e >> 7, j = e & 127;
        float s = 0.f;
#pragma unroll
        for (int k = 0; k < 32; k++) s += G[k * 128 + i] * G[k * 128 + j];
        g_A0[e] = -0.5f * (Q[e] + s + ((i == j) ? EPSc : 0.f)) + S[e];
    }
}

// ---------------- spectral: ||Q||_F + Lanczos lam_max(HtH) ----------------
__global__ void k_spec(const float* __restrict__ Qm) {
    __shared__ float sM[64 * 64], v[64], vp[64], red[64], al[LAN_M], be[LAN_M + 1];
    int t = threadIdx.x;
    for (int i = t; i < 4096; i += 64) sM[i] = g_HtH[i];
    float s = 0.f;
    for (int i = t; i < 16384; i += 64) { float q = Qm[i]; s += q * q; }
    red[t] = s; __syncthreads();
    for (int o = 32; o > 0; o >>= 1) { if (t < o) red[t] += red[t + o]; __syncthreads(); }
    float cfro = sqrtf(red[0]); __syncthreads();
    float rs = 0.f;
    for (int k = 0; k < 64; k++) rs += sM[t * 64 + k];
    red[t] = rs * rs; __syncthreads();
    for (int o = 32; o > 0; o >>= 1) { if (t < o) red[t] += red[t + o]; __syncthreads(); }
    float n0 = sqrtf(red[0]); __syncthreads();
    v[t] = rs / n0; vp[t] = 0.f;
    if (t == 0) be[0] = 0.f;
    __syncthreads();
    for (int j = 0; j < LAN_M; j++) {
        float acc = 0.f;
#pragma unroll 8
        for (int k = 0; k < 64; k++) acc += sM[t * 64 + k] * v[k];
        float wi = acc - be[j] * vp[t];
        red[t] = wi * v[t]; __syncthreads();
        for (int o = 32; o > 0; o >>= 1) { if (t < o) red[t] += red[t + o]; __syncthreads(); }
        float a = red[0]; __syncthreads();
        if (t == 0) al[j] = a;
        wi -= a * v[t];
        red[t] = wi * wi; __syncthreads();
        for (int o = 32; o > 0; o >>= 1) { if (t < o) red[t] += red[t + o]; __syncthreads(); }
        float bn = sqrtf(red[0]); __syncthreads();
        if (t == 0) be[j + 1] = bn;
        vp[t] = v[t];
        v[t] = (bn > 1e-12f) ? (wi / bn) : 0.f;
        __syncthreads();
    }
    if (t == 0) {
        double hi = 0.0, lo = 0.0;
        for (int j = 0; j < LAN_M; j++) {
            double g = (double)al[j] + fabs((double)be[j]) + fabs((double)be[j + 1]);
            if (g > hi) hi = g;
        }
        hi += 1.0;
        for (int it = 0; it < 60; ++it) {
            double xm = 0.5 * (lo + hi);
            int cnt = 0; double d = 1.0;
            for (int j = 0; j < LAN_M; j++) {
                double bj = (j == 0) ? 0.0 : (double)be[j];
                d = ((double)al[j] - xm) - bj * bj / d;
                if (d == 0.0) d = -1e-300;
                if (d < 0.0) cnt++;
            }
            if (cnt >= LAN_M) hi = xm; else lo = xm;
        }
        double lam = 0.5 * (lo + hi);
        if (lam < 1e-20) lam = 1e-20;
        g_scal[0] = 1.0f / cfro;
        g_scal[1] = (float)(sqrt((double)cfro) / (1.01 * sqrt(lam)));
    }
}

// ---------------- init: A = A0@P ; C = G@P ; Y0 = Q/c ; Z0 = I ; reset barrier ----------------
__global__ void k_init(const float* __restrict__ P, const float* __restrict__ G,
                       const float* __restrict__ Qm) {
    int b = blockIdx.x, t = threadIdx.x;
    if (b == 0 && t == 0) g_cnt = 0u;
    if (b < 64) {
        int e = b * 256 + t, i = e >> 7, j = e & 127;
        const float* a0 = &g_A0[i * 128];
        float s = 0.f;
#pragma unroll 8
        for (int k = 0; k < 128; k++) s += a0[k] * P[k * 128 + j];
        g_A[e] = s;
    } else if (b < 80) {
        int e = (b - 64) * 256 + t, i = e >> 7, j = e & 127;
        const float* gi = &G[i * 128];
        float s = 0.f;
#pragma unroll 8
        for (int k = 0; k < 128; k++) s += gi[k] * P[k * 128 + j];
        g_C[e] = s;
    } else {
        float ic = g_scal[0];
        int base = (b - 80) * 1024 + t;
#pragma unroll
        for (int r = 0; r < 4; r++) {
            int idx = base + r * 256;
            if (idx < 16384) g_Ybuf[0][idx] = Qm[idx] * ic;
            else { int e2 = idx - 16384; g_Zbuf[0][e2] = ((e2 >> 7) == (e2 & 127)) ? 1.f : 0.f; }
        }
    }
}

// ---------------- fused Newton-Schulz with grid spin barrier ----------------
__device__ __forceinline__ void gridbar(unsigned target) {
    __syncthreads();
    if (threadIdx.x == 0) {
        __threadfence();
        atomicAdd(&g_cnt, 1u);
        while (*((volatile unsigned*)&g_cnt) < target) { }
        __threadfence();
    }
    __syncthreads();
}

__global__ void __launch_bounds__(256, 1) k_ns_fused() {
    __shared__ float rows[2][128];
    int b = blockIdx.x, t = threadIdx.x;
    int p = 0;
    unsigned nb = 0;
    for (int it = 0; it < NS_ITERS; it++) {
        const float* Y = g_Ybuf[p];
        const float* Z = g_Zbuf[p];
        float* Yn = g_Ybuf[p ^ 1];
        float* Zn = g_Zbuf[p ^ 1];
        if (b < 64) {               // T = 1.5I - 0.5 Z@Y
            int i0 = b * 2;
            rows[t >> 7][t & 127] = Z[i0 * 128 + t];
            __syncthreads();
            int i = t >> 7, j = t & 127;
            const float* rw = rows[i];
            float s = 0.f;
#pragma unroll 8
            for (int k = 0; k < 128; k++) s += rw[k] * Y[k * 128 + j];
            g_T[(i0 + i) * 128 + j] = (((i0 + i) == j) ? 1.5f : 0.f) - 0.5f * s;
        }
        nb++; gridbar(nb * NSGRID);
        if (b < 64) {               // Yn = Y@T
            int i0 = b * 2;
            rows[t >> 7][t & 127] = Y[i0 * 128 + t];
            __syncthreads();
            int i = t >> 7, j = t & 127;
            const float* rw = rows[i];
            float s = 0.f;
#pragma unroll 8
            for (int k = 0; k < 128; k++) s += rw[k] * g_T[k * 128 + j];
            Yn[(i0 + i) * 128 + j] = s;
        } else {                    // Zn = T@Z
            int i0 = (b - 64) * 2;
            rows[t >> 7][t & 127] = g_T[i0 * 128 + t];
            __syncthreads();
            int i = t >> 7, j = t & 127;
            const float* rw = rows[i];
            float s = 0.f;
#pragma unroll 8
            for (int k = 0; k < 128; k++) s += rw[k] * Z[k * 128 + j];
            Zn[(i0 + i) * 128 + j] = s;
        }
        nb++; gridbar(nb * NSGRID);
        p ^= 1;
    }
}

// ---------------- B = scale * Yfinal @ H  (Yfinal = g_Ybuf[0] after 16 iters) ----------------
__global__ void k_B(const float* __restrict__ H) {
    const float* Yf = g_Ybuf[0];
    int e = blockIdx.x * 256 + threadIdx.x, i = e >> 6, j = e & 63;
    const float* yr = &Yf[i * 128];
    float s = 0.f;
#pragma unroll 8
    for (int k = 0; k < 128; k++) s += yr[k] * H[k * 64 + j];
    g_B[e] = s * g_scal[1];
}

// ---------------- pack W into SW128-swizzled bf16 hi/lo image ----------------
__global__ void k_packW() {
    int idx = blockIdx.x * 256 + threadIdx.x;     // 120 x 256 = 30720 = 160*192
    int o = idx / 192, k = idx % 192;
    float v;
    if (k < 128) v = (o < 128) ? g_A[o * 128 + k] : g_C[(o - 128) * 128 + k];
    else         v = (o < 128) ? g_B[o * 64 + (k - 128)] : 0.f;
    __nv_bfloat16 h = __float2bfloat16_rn(v);
    __nv_bfloat16 l = __float2bfloat16_rn(v - __bfloat162float(h));
    uint32_t boff = (uint32_t)(((o >> 3) + (k >> 6) * 20) * 1024 + (o & 7) * 128 + (k & 63) * 2);
    uint32_t sw = boff ^ ((boff >> 3) & 0x70);
    *(unsigned short*)(g_Wimg + sw) = __bfloat16_as_ushort(h);
    *(unsigned short*)(g_Wimg + W_IMG_HALF + sw) = __bfloat16_as_ushort(l);
}

// ---------------- main GEMM: tcgen05 bf16 split, persistent CTAs ----------------
__device__ __forceinline__ uint32_t pack2(float a, float b, float& ra, float& rb) {
    __nv_bfloat16 ha = __float2bfloat16_rn(a), hb = __float2bfloat16_rn(b);
    ra = a - __bfloat162float(ha);
    rb = b - __bfloat162float(hb);
    return (uint32_t)__bfloat16_as_ushort(ha) | ((uint32_t)__bfloat16_as_ushort(hb) << 16);
}

#if TC_OK
__device__ __forceinline__ void epilogue(uint32_t dcol, int tile, int t,
                                         float* __restrict__ dx, float* __restrict__ y) {
    size_t srow = (size_t)tile * 128 + t;
    uint32_t r[32];
#pragma unroll
    for (int g = 0; g < 4; g++) {
        TCGEN05_LD_X32(r, dcol + g * 32);
        TCGEN05_WAIT_LD();
        float4* dst = (float4*)&dx[srow * 128 + g * 32];
#pragma unroll
        for (int q = 0; q < 8; q++)
            dst[q] = make_float4(__uint_as_float(r[4 * q]), __uint_as_float(r[4 * q + 1]),
                                 __uint_as_float(r[4 * q + 2]), __uint_as_float(r[4 * q + 3]));
    }
    TCGEN05_LD_X32(r, dcol + 128);
    TCGEN05_WAIT_LD();
    TCGEN05_FENCE_BEFORE();
    float4* dy = (float4*)&y[srow * 32];
#pragma unroll
    for (int q = 0; q < 8; q++)
        dy[q] = make_float4(__uint_as_float(r[4 * q]), __uint_as_float(r[4 * q + 1]),
                            __uint_as_float(r[4 * q + 2]), __uint_as_float(r[4 * q + 3]));
}
#endif

__global__ void __launch_bounds__(128, 1) k_main(
    const float* __restrict__ x, const float* __restrict__ u,
    float* __restrict__ dx, float* __restrict__ y, int ntiles) {
#if TC_OK
    extern __shared__ unsigned char smraw[];
    __shared__ uint32_t s_tptr;
    __shared__ __align__(8) unsigned long long s_mbar;
    int t = threadIdx.x;
    uint32_t smbase = smem_u32(smraw);
    uint32_t wbase = (smbase + 1023u) & ~1023u;
    unsigned char* wptr = smraw + (wbase - smbase);
    {   // copy pre-swizzled W image (hi+lo) to smem
        const float4* src = (const float4*)g_Wimg;
        float4* dst = (float4*)wptr;
        for (int i = t; i < W_IMG_BYTES / 16; i += 128) dst[i] = src[i];
    }
    if (t < 32) { TCGEN05_ALLOC(smem_u32(&s_tptr), 512); TCGEN05_RELINQ(); }
    if (t == 0) MBARRIER_INIT(smem_u32(&s_mbar), 1);
    __syncthreads();
    uint32_t tb = s_tptr;
    uint32_t mb = smem_u32(&s_mbar);
    uint64_t descH = make_desc(wbase);
    uint64_t descL = make_desc(wbase + W_IMG_HALF);
    uint32_t wofs = (uint32_t)(t >> 5) << 21;
    uint32_t parity = 0;
    int prev = -1;
    int buf = 0, prevbuf = 0;      // explicit D double-buffer (BUGFIX: tile&1 was constant)

    for (int tile = blockIdx.x; tile < ntiles; tile += gridDim.x) {
        size_t sbase = (size_t)tile * 128;
        const float* xr = &x[(sbase + t) * 128];
        const float* ur = &u[(sbase + t) * 64];
        if (prev >= 0) { MBARRIER_WAIT_PARITY(mb, parity); parity ^= 1; TCGEN05_FENCE_AFTER(); }
        // convert 192 fp32 -> bf16 hi (TMEM cols 0..95) + lo (96..191)
#pragma unroll
        for (int c = 0; c < 6; c++) {
            const float4* s4 = (c < 4) ? (const float4*)(xr + 32 * c) : (const float4*)(ur + 32 * (c - 4));
            float4 v[8];
#pragma unroll
            for (int q = 0; q < 8; q++) v[q] = s4[q];
            uint32_t hi[16], lo[16];
#pragma unroll
            for (int q = 0; q < 8; q++) {
                float r0, r1, r2, r3, d0, d1;
                hi[2 * q]     = pack2(v[q].x, v[q].y, r0, r1);
                hi[2 * q + 1] = pack2(v[q].z, v[q].w, r2, r3);
                lo[2 * q]     = pack2(r0, r1, d0, d1);
                lo[2 * q + 1] = pack2(r2, r3, d0, d1);
            }
            TCGEN05_ST_X16(tb + (uint32_t)(c * 16) + wofs, hi);
            TCGEN05_ST_X16(tb + (uint32_t)(96 + c * 16) + wofs, lo);
        }
        TCGEN05_WAIT_ST();
        TCGEN05_FENCE_BEFORE();
        __syncthreads();
        uint32_t dcol = tb + 192u + (uint32_t)buf * 160u;
        if (t < 32) {
            TCGEN05_FENCE_AFTER();
            if (elect_one_pred()) {
                int idx = 0;
#pragma unroll
                for (int term = 0; term < 3; term++) {
                    uint32_t ab = tb + ((term == 2) ? 96u : 0u);
                    uint64_t bd = (term == 1) ? descL : descH;
#pragma unroll
                    for (int k = 0; k < 12; k++) {
                        uint64_t d = bd + (uint64_t)((k >> 2) * 1280 + (k & 3) * 2);
                        TCGEN05_MMA_F16(dcol, ab + (uint32_t)(k * 8), d, IDESC_MAIN, idx > 0);
                        idx++;
                    }
                }
                TCGEN05_COMMIT(mb);
            }
        }
        if (prev >= 0) epilogue(tb + 192u + (uint32_t)prevbuf * 160u, prev, t, dx, y);
        prev = tile;
        prevbuf = buf;
        buf ^= 1;
    }
    if (prev >= 0) {
        MBARRIER_WAIT_PARITY(mb, parity); parity ^= 1;
        TCGEN05_FENCE_AFTER();
        epilogue(tb + 192u + (uint32_t)prevbuf * 160u, prev, t, dx, y);
    }
    __syncthreads();
    if (t < 32) TCGEN05_DEALLOC(tb, 512);
#else
    // Generic-PTX fallback (never executed on GB300: sm_103a SASS is loaded).
    int t = threadIdx.x;
    for (int tile = blockIdx.x; tile < ntiles; tile += gridDim.x) {
        size_t s = (size_t)tile * 128 + t;
        const float* xr = &x[s * 128];
        const float* ur = &u[s * 64];
        for (int o = 0; o < 128; o++) {
            float acc = 0.f;
            for (int k = 0; k < 128; k++) acc += xr[k] * g_A[o * 128 + k];
            for (int k = 0; k < 64; k++)  acc += ur[k] * g_B[o * 64 + k];
            dx[s * 128 + o] = acc;
        }
        for (int o = 0; o < 32; o++) {
            float acc = 0.f;
            for (int k = 0; k < 128; k++) acc += xr[k] * g_C[o * 128 + k];
            y[s * 32 + o] = acc;
        }
    }
#endif
}

// ---------------- launcher ----------------
extern "C" void kernel_launch(void* const* d_in, const int* in_sizes, int n_in,
                              void* d_out, int out_size) {
    const float* u = (const float*)d_in[0];
    const float* x = (const float*)d_in[1];
    const float* Q = (const float*)d_in[2];
    const float* P = (const float*)d_in[3];
    const float* S = (const float*)d_in[4];
    const float* G = (const float*)d_in[5];
    const float* H = (const float*)d_in[6];
    int N = in_sizes[0] / 64;
    float* dx = (float*)d_out;
    float* y = dx + (size_t)N * 128;

    k_prep1<<<80, 256>>>(Q, S, G, H);
    k_spec<<<1, 64>>>(Q);
    k_init<<<112, 256>>>(P, G, Q);
    k_ns_fused<<<NSGRID, 256>>>();
    k_B<<<32, 256>>>(H);
    k_packW<<<120, 256>>>();

    int smem = 1024 + W_IMG_BYTES + 64;
    cudaFuncSetAttribute(k_main, cudaFuncAttributeMaxDynamicSharedMemorySize, smem);
    int ntiles = N / 128;
    k_main<<<152, 128, smem>>>(x, u, dx, y, ntiles);
}

// round 6
// speedup vs baseline: 6.4734x; 5.3936x over previous
#include <cuda_runtime.h>
#include <cuda_bf16.h>
#include <math.h>
#include <stdint.h>

#define NS_ITERS 16
#define LAN_M 56
#define EPSc 1e-4f
#define NSGRID 128
#define IDESC_MAIN 0x8280490u   // f32 accum, bf16 a/b, M=128, N=160
#define W_IMG_HALF 61440
#define W_IMG_BYTES 122880

// tcgen05 only exists on arch-specific targets (sm_103a). The harness also
// runs a generic compute_103 PTX pass, which must compile a fallback.
#if !defined(__CUDA_ARCH__) || defined(__CUDA_ARCH_FEAT_SM103_ALL) || defined(__CUDA_ARCH_FEAT_SM100_ALL)
#define TC_OK 1
#else
#define TC_OK 0
#endif

// ---------------- PTX helpers ----------------
__device__ __forceinline__ uint32_t smem_u32(const void* p) {
    uint32_t a;
    asm("{ .reg .u64 t; cvta.to.shared.u64 t, %1; cvt.u32.u64 %0, t; }" : "=r"(a) : "l"(p));
    return a;
}
__device__ __forceinline__ uint32_t elect_one_pred() {
    uint32_t pred;
    asm volatile("{\n\t.reg .pred p;\n\telect.sync _|p, 0xFFFFFFFF;\n\tselp.b32 %0, 1, 0, p;\n\t}" : "=r"(pred));
    return pred;
}
#define TCGEN05_ALLOC(a, n) asm volatile("tcgen05.alloc.cta_group::1.sync.aligned.shared::cta.b32 [%0], %1;" :: "r"((uint32_t)(a)), "r"((uint32_t)(n)) : "memory")
#define TCGEN05_DEALLOC(a, n) asm volatile("tcgen05.dealloc.cta_group::1.sync.aligned.b32 %0, %1;" :: "r"(a), "r"((uint32_t)(n)))
#define TCGEN05_RELINQ() asm volatile("tcgen05.relinquish_alloc_permit.cta_group::1.sync.aligned;")
#define TCGEN05_WAIT_ST() asm volatile("tcgen05.wait::st.sync.aligned;" ::: "memory")
#define TCGEN05_WAIT_LD() asm volatile("tcgen05.wait::ld.sync.aligned;" ::: "memory")
#define TCGEN05_FENCE_BEFORE() asm volatile("tcgen05.fence::before_thread_sync;" ::: "memory")
#define TCGEN05_FENCE_AFTER()  asm volatile("tcgen05.fence::after_thread_sync;" ::: "memory")
#define TCGEN05_COMMIT(m) asm volatile("tcgen05.commit.cta_group::1.mbarrier::arrive::one.shared::cluster.b64 [%0];" :: "r"((uint32_t)(m)) : "memory")
#define MBARRIER_INIT(m, c) asm volatile("mbarrier.init.shared.b64 [%0], %1;" :: "r"((uint32_t)(m)), "r"((uint32_t)(c)) : "memory")
#define MBARRIER_WAIT_PARITY(m, ph) do { \
    uint32_t _m = (uint32_t)(m), _p = (uint32_t)(ph), _d; \
    asm volatile("{\n\t.reg .pred p;\n\tmbarrier.try_wait.parity.acquire.cta.shared::cta.b64 p, [%1], %2;\n\tselp.b32 %0, 1, 0, p;\n\t}" : "=r"(_d) : "r"(_m), "r"(_p) : "memory"); \
    if (!_d) { asm volatile("{\n\t.reg .pred P1;\n\tWL_%=:\n\tmbarrier.try_wait.parity.acquire.cta.shared::cta.b64 P1, [%0], %1, 0x989680;\n\t@P1 bra.uni WD_%=;\n\tbra.uni WL_%=;\n\tWD_%=:\n\t}" :: "r"(_m), "r"(_p) : "memory"); } \
} while (0)
#define TCGEN05_MMA_F16(d, a, bd, id, en) do { \
    uint32_t _e = (en) ? 1 : 0, _z = 0; \
    asm volatile("{\n\t.reg .pred p;\n\tsetp.ne.u32 p, %6, 0;\n\ttcgen05.mma.cta_group::1.kind::f16 [%0], [%1], %2, %3, {%4, %4, %4, %4}, p;\n\t}" \
        :: "r"(d), "r"(a), "l"(bd), "r"(id), "r"(_z), "r"(_z), "r"(_e) : "memory"); \
} while (0)
#define TCGEN05_ST_X16(a, r) asm volatile("tcgen05.st.sync.aligned.32x32b.x16.b32 [%0], {%1,%2,%3,%4,%5,%6,%7,%8,%9,%10,%11,%12,%13,%14,%15,%16};" \
    :: "r"(a), "r"((r)[0]), "r"((r)[1]), "r"((r)[2]), "r"((r)[3]), "r"((r)[4]), "r"((r)[5]), "r"((r)[6]), "r"((r)[7]), \
       "r"((r)[8]), "r"((r)[9]), "r"((r)[10]), "r"((r)[11]), "r"((r)[12]), "r"((r)[13]), "r"((r)[14]), "r"((r)[15]) : "memory")
#define TCGEN05_LD_X32(r, a) asm volatile("tcgen05.ld.sync.aligned.32x32b.x32.b32 {%0,%1,%2,%3,%4,%5,%6,%7,%8,%9,%10,%11,%12,%13,%14,%15,%16,%17,%18,%19,%20,%21,%22,%23,%24,%25,%26,%27,%28,%29,%30,%31}, [%32];" \
    : "=r"((r)[0]), "=r"((r)[1]), "=r"((r)[2]), "=r"((r)[3]), "=r"((r)[4]), "=r"((r)[5]), "=r"((r)[6]), "=r"((r)[7]), \
      "=r"((r)[8]), "=r"((r)[9]), "=r"((r)[10]), "=r"((r)[11]), "=r"((r)[12]), "=r"((r)[13]), "=r"((r)[14]), "=r"((r)[15]), \
      "=r"((r)[16]), "=r"((r)[17]), "=r"((r)[18]), "=r"((r)[19]), "=r"((r)[20]), "=r"((r)[21]), "=r"((r)[22]), "=r"((r)[23]), \
      "=r"((r)[24]), "=r"((r)[25]), "=r"((r)[26]), "=r"((r)[27]), "=r"((r)[28]), "=r"((r)[29]), "=r"((r)[30]), "=r"((r)[31]) : "r"(a))
static __device__ __forceinline__ uint64_t make_desc(uint32_t addr) {
    return ((uint64_t)2 << 61) | ((uint64_t)1 << 46) | ((uint64_t)64 << 32) | ((uint64_t)1 << 16)
         | ((uint64_t)(addr >> 4) & 0x3FFF);
}

// ---------------- device scratch ----------------
__device__ float g_HtH[64 * 64];
__device__ float g_A0[128 * 128];
__device__ float g_A[128 * 128];
__device__ float g_B[128 * 64];
__device__ float g_C[32 * 128];
__device__ float g_Ybuf[2][128 * 128];
__device__ float g_Zbuf[2][128 * 128];
__device__ float g_T[128 * 128];
__device__ float g_scal[2];
__device__ unsigned g_cnt;
__device__ __align__(16) unsigned char g_Wimg[W_IMG_BYTES];

// ---------------- setup: HtH + A0 ----------------
__global__ void k_prep1(const float* __restrict__ Q, const float* __restrict__ S,
                        const float* __restrict__ G, const float* __restrict__ H) {
    int b = blockIdx.x, t = threadIdx.x;
    if (b < 16) {
        int e = b * 256 + t, i = e >> 6, j = e & 63;
        float s = 0.f;
#pragma unroll 8
        for (int k = 0; k < 128; k++) s += H[k * 64 + i] * H[k * 64 + j];
        g_HtH[e] = s;
    } else {
        int e = (b - 16) * 256 + t, i = e >> 7, j = e & 127;
        float s = 0.f;
#pragma unroll
        for (int k = 0; k < 32; k++) s += G[k * 128 + i] * G[k * 128 + j];
        g_A0[e] = -0.5f * (Q[e] + s + ((i == j) ? EPSc : 0.f)) + S[e];
    }
}

// ---------------- spectral: ||Q||_F + Lanczos lam_max(HtH) ----------------
// Bisection replaced by 64-way fp32 multisection (5 rounds) — kills the
// single-thread double-divide chain (~1.3 ms -> ~8 us).
__global__ void k_spec(const float* __restrict__ Qm) {
    __shared__ float sM[64 * 64], v[64], vp[64], red[64], al[LAN_M], be[LAN_M + 1];
    __shared__ float slo, shi;
    __shared__ int sflag[64];
    int t = threadIdx.x;
    for (int i = t; i < 4096; i += 64) sM[i] = g_HtH[i];
    float s = 0.f;
    for (int i = t; i < 16384; i += 64) { float q = Qm[i]; s += q * q; }
    red[t] = s; __syncthreads();
    for (int o = 32; o > 0; o >>= 1) { if (t < o) red[t] += red[t + o]; __syncthreads(); }
    float cfro = sqrtf(red[0]); __syncthreads();
    float rs = 0.f;
    for (int k = 0; k < 64; k++) rs += sM[t * 64 + k];
    red[t] = rs * rs; __syncthreads();
    for (int o = 32; o > 0; o >>= 1) { if (t < o) red[t] += red[t + o]; __syncthreads(); }
    float n0 = sqrtf(red[0]); __syncthreads();
    v[t] = rs / n0; vp[t] = 0.f;
    if (t == 0) be[0] = 0.f;
    __syncthreads();
    for (int j = 0; j < LAN_M; j++) {
        float acc = 0.f;
#pragma unroll 8
        for (int k = 0; k < 64; k++) acc += sM[t * 64 + k] * v[k];
        float wi = acc - be[j] * vp[t];
        red[t] = wi * v[t]; __syncthreads();
        for (int o = 32; o > 0; o >>= 1) { if (t < o) red[t] += red[t + o]; __syncthreads(); }
        float a = red[0]; __syncthreads();
        if (t == 0) al[j] = a;
        wi -= a * v[t];
        red[t] = wi * wi; __syncthreads();
        for (int o = 32; o > 0; o >>= 1) { if (t < o) red[t] += red[t + o]; __syncthreads(); }
        float bn = sqrtf(red[0]); __syncthreads();
        if (t == 0) be[j + 1] = bn;
        vp[t] = v[t];
        v[t] = (bn > 1e-12f) ? (wi / bn) : 0.f;
        __syncthreads();
    }
    if (t == 0) {
        float hi = 0.f;
        for (int j = 0; j < LAN_M; j++) {
            float g = al[j] + fabsf(be[j]) + fabsf(be[j + 1]);
            if (g > hi) hi = g;
        }
        slo = 0.f; shi = hi + 1.f;
    }
    __syncthreads();
    // 5 rounds of 64-way multisection for lambda_max of tridiag(al, be)
    for (int r = 0; r < 5; r++) {
        float lo = slo, hi = shi;
        float xm = lo + (hi - lo) * (float)(t + 1) * (1.f / 65.f);
        int cnt = 0; float d = 1.f;
        for (int j = 0; j < LAN_M; j++) {
            float bj = (j == 0) ? 0.f : be[j];
            d = (al[j] - xm) - __fdividef(bj * bj, d);
            if (d == 0.f) d = -1e-30f;
            if (d < 0.f) cnt++;
        }
        sflag[t] = (cnt >= LAN_M) ? 1 : 0;   // shift above lambda_max
        __syncthreads();
        if (t == 0) {
            float nlo = lo, nhi = hi;
            for (int q = 0; q < 64; q++) {
                float sq = lo + (hi - lo) * (float)(q + 1) * (1.f / 65.f);
                if (sflag[q]) { nhi = sq; break; }
                nlo = sq;
            }
            slo = nlo; shi = nhi;
        }
        __syncthreads();
    }
    if (t == 0) {
        float lam = 0.5f * (slo + shi);
        if (lam < 1e-20f) lam = 1e-20f;
        g_scal[0] = 1.0f / cfro;
        g_scal[1] = sqrtf(cfro) / (1.01f * sqrtf(lam));
    }
}

// ---------------- init: A = A0@P ; C = G@P ; Y0 = Q/c ; Z0 = I ; reset barrier ----------------
__global__ void k_init(const float* __restrict__ P, const float* __restrict__ G,
                       const float* __restrict__ Qm) {
    int b = blockIdx.x, t = threadIdx.x;
    if (b == 0 && t == 0) g_cnt = 0u;
    if (b < 64) {
        int e = b * 256 + t, i = e >> 7, j = e & 127;
        const float* a0 = &g_A0[i * 128];
        float s = 0.f;
#pragma unroll 8
        for (int k = 0; k < 128; k++) s += a0[k] * P[k * 128 + j];
        g_A[e] = s;
    } else if (b < 80) {
        int e = (b - 64) * 256 + t, i = e >> 7, j = e & 127;
        const float* gi = &G[i * 128];
        float s = 0.f;
#pragma unroll 8
        for (int k = 0; k < 128; k++) s += gi[k] * P[k * 128 + j];
        g_C[e] = s;
    } else {
        float ic = g_scal[0];
        int base = (b - 80) * 1024 + t;
#pragma unroll
        for (int r = 0; r < 4; r++) {
            int idx = base + r * 256;
            if (idx < 16384) g_Ybuf[0][idx] = Qm[idx] * ic;
            else { int e2 = idx - 16384; g_Zbuf[0][e2] = ((e2 >> 7) == (e2 & 127)) ? 1.f : 0.f; }
        }
    }
}

// ---------------- fused Newton-Schulz with grid spin barrier ----------------
__device__ __forceinline__ void gridbar(unsigned target) {
    __syncthreads();
    if (threadIdx.x == 0) {
        __threadfence();
        atomicAdd(&g_cnt, 1u);
        while (*((volatile unsigned*)&g_cnt) < target) { }
        __threadfence();
    }
    __syncthreads();
}

__global__ void __launch_bounds__(256, 1) k_ns_fused() {
    __shared__ float rows[2][128];
    int b = blockIdx.x, t = threadIdx.x;
    int p = 0;
    unsigned nb = 0;
    for (int it = 0; it < NS_ITERS; it++) {
        const float* Y = g_Ybuf[p];
        const float* Z = g_Zbuf[p];
        float* Yn = g_Ybuf[p ^ 1];
        float* Zn = g_Zbuf[p ^ 1];
        if (b < 64) {               // T = 1.5I - 0.5 Z@Y
            int i0 = b * 2;
            rows[t >> 7][t & 127] = Z[i0 * 128 + t];
            __syncthreads();
            int i = t >> 7, j = t & 127;
            const float* rw = rows[i];
            float s = 0.f;
#pragma unroll 8
            for (int k = 0; k < 128; k++) s += rw[k] * Y[k * 128 + j];
            g_T[(i0 + i) * 128 + j] = (((i0 + i) == j) ? 1.5f : 0.f) - 0.5f * s;
        }
        nb++; gridbar(nb * NSGRID);
        if (b < 64) {               // Yn = Y@T
            int i0 = b * 2;
            rows[t >> 7][t & 127] = Y[i0 * 128 + t];
            __syncthreads();
            int i = t >> 7, j = t & 127;
            const float* rw = rows[i];
            float s = 0.f;
#pragma unroll 8
            for (int k = 0; k < 128; k++) s += rw[k] * g_T[k * 128 + j];
            Yn[(i0 + i) * 128 + j] = s;
        } else {                    // Zn = T@Z
            int i0 = (b - 64) * 2;
            rows[t >> 7][t & 127] = g_T[i0 * 128 + t];
            __syncthreads();
            int i = t >> 7, j = t & 127;
            const float* rw = rows[i];
            float s = 0.f;
#pragma unroll 8
            for (int k = 0; k < 128; k++) s += rw[k] * Z[k * 128 + j];
            Zn[(i0 + i) * 128 + j] = s;
        }
        nb++; gridbar(nb * NSGRID);
        p ^= 1;
    }
}

// ---------------- B = scale * Yfinal @ H  (Yfinal = g_Ybuf[0] after 16 iters) ----------------
__global__ void k_B(const float* __restrict__ H) {
    const float* Yf = g_Ybuf[0];
    int e = blockIdx.x * 256 + threadIdx.x, i = e >> 6, j = e & 63;
    const float* yr = &Yf[i * 128];
    float s = 0.f;
#pragma unroll 8
    for (int k = 0; k < 128; k++) s += yr[k] * H[k * 64 + j];
    g_B[e] = s * g_scal[1];
}

// ---------------- pack W into SW128-swizzled bf16 hi/lo image ----------------
__global__ void k_packW() {
    int idx = blockIdx.x * 256 + threadIdx.x;     // 120 x 256 = 30720 = 160*192
    int o = idx / 192, k = idx % 192;
    float v;
    if (k < 128) v = (o < 128) ? g_A[o * 128 + k] : g_C[(o - 128) * 128 + k];
    else         v = (o < 128) ? g_B[o * 64 + (k - 128)] : 0.f;
    __nv_bfloat16 h = __float2bfloat16_rn(v);
    __nv_bfloat16 l = __float2bfloat16_rn(v - __bfloat162float(h));
    uint32_t boff = (uint32_t)(((o >> 3) + (k >> 6) * 20) * 1024 + (o & 7) * 128 + (k & 63) * 2);
    uint32_t sw = boff ^ ((boff >> 3) & 0x70);
    *(unsigned short*)(g_Wimg + sw) = __bfloat16_as_ushort(h);
    *(unsigned short*)(g_Wimg + W_IMG_HALF + sw) = __bfloat16_as_ushort(l);
}

// ---------------- main GEMM: tcgen05 bf16 split, persistent CTAs ----------------
__device__ __forceinline__ uint32_t pack2(float a, float b, float& ra, float& rb) {
    __nv_bfloat16 ha = __float2bfloat16_rn(a), hb = __float2bfloat16_rn(b);
    ra = a - __bfloat162float(ha);
    rb = b - __bfloat162float(hb);
    return (uint32_t)__bfloat16_as_ushort(ha) | ((uint32_t)__bfloat16_as_ushort(hb) << 16);
}

#if TC_OK
__device__ __forceinline__ void epilogue(uint32_t dcol, int tile, int t,
                                         float* __restrict__ dx, float* __restrict__ y) {
    size_t srow = (size_t)tile * 128 + t;
    uint32_t r[32];
#pragma unroll
    for (int g = 0; g < 4; g++) {
        TCGEN05_LD_X32(r, dcol + g * 32);
        TCGEN05_WAIT_LD();
        float4* dst = (float4*)&dx[srow * 128 + g * 32];
#pragma unroll
        for (int q = 0; q < 8; q++)
            dst[q] = make_float4(__uint_as_float(r[4 * q]), __uint_as_float(r[4 * q + 1]),
                                 __uint_as_float(r[4 * q + 2]), __uint_as_float(r[4 * q + 3]));
    }
    TCGEN05_LD_X32(r, dcol + 128);
    TCGEN05_WAIT_LD();
    TCGEN05_FENCE_BEFORE();
    float4* dy = (float4*)&y[srow * 32];
#pragma unroll
    for (int q = 0; q < 8; q++)
        dy[q] = make_float4(__uint_as_float(r[4 * q]), __uint_as_float(r[4 * q + 1]),
                            __uint_as_float(r[4 * q + 2]), __uint_as_float(r[4 * q + 3]));
}
#endif

__global__ void __launch_bounds__(128, 1) k_main(
    const float* __restrict__ x, const float* __restrict__ u,
    float* __restrict__ dx, float* __restrict__ y, int ntiles) {
#if TC_OK
    extern __shared__ unsigned char smraw[];
    __shared__ uint32_t s_tptr;
    __shared__ __align__(8) unsigned long long s_mbar;
    int t = threadIdx.x;
    uint32_t smbase = smem_u32(smraw);
    uint32_t wbase = (smbase + 1023u) & ~1023u;
    unsigned char* wptr = smraw + (wbase - smbase);
    {   // copy pre-swizzled W image (hi+lo) to smem
        const float4* src = (const float4*)g_Wimg;
        float4* dst = (float4*)wptr;
        for (int i = t; i < W_IMG_BYTES / 16; i += 128) dst[i] = src[i];
    }
    if (t < 32) { TCGEN05_ALLOC(smem_u32(&s_tptr), 512); TCGEN05_RELINQ(); }
    if (t == 0) MBARRIER_INIT(smem_u32(&s_mbar), 1);
    __syncthreads();
    uint32_t tb = s_tptr;
    uint32_t mb = smem_u32(&s_mbar);
    uint64_t descH = make_desc(wbase);
    uint64_t descL = make_desc(wbase + W_IMG_HALF);
    uint32_t wofs = (uint32_t)(t >> 5) << 21;
    uint32_t parity = 0;
    int prev = -1;
    int buf = 0, prevbuf = 0;      // explicit D double-buffer

    for (int tile = blockIdx.x; tile < ntiles; tile += gridDim.x) {
        size_t sbase = (size_t)tile * 128;
        const float* xr = &x[(sbase + t) * 128];
        const float* ur = &u[(sbase + t) * 64];
        if (prev >= 0) { MBARRIER_WAIT_PARITY(mb, parity); parity ^= 1; TCGEN05_FENCE_AFTER(); }
        // convert 192 fp32 -> bf16 hi (TMEM cols 0..95) + lo (96..191)
#pragma unroll
        for (int c = 0; c < 6; c++) {
            const float4* s4 = (c < 4) ? (const float4*)(xr + 32 * c) : (const float4*)(ur + 32 * (c - 4));
            float4 v[8];
#pragma unroll
            for (int q = 0; q < 8; q++) v[q] = s4[q];
            uint32_t hi[16], lo[16];
#pragma unroll
            for (int q = 0; q < 8; q++) {
                float r0, r1, r2, r3, d0, d1;
                hi[2 * q]     = pack2(v[q].x, v[q].y, r0, r1);
                hi[2 * q + 1] = pack2(v[q].z, v[q].w, r2, r3);
                lo[2 * q]     = pack2(r0, r1, d0, d1);
                lo[2 * q + 1] = pack2(r2, r3, d0, d1);
            }
            TCGEN05_ST_X16(tb + (uint32_t)(c * 16) + wofs, hi);
            TCGEN05_ST_X16(tb + (uint32_t)(96 + c * 16) + wofs, lo);
        }
        TCGEN05_WAIT_ST();
        TCGEN05_FENCE_BEFORE();
        __syncthreads();
        uint32_t dcol = tb + 192u + (uint32_t)buf * 160u;
        if (t < 32) {
            TCGEN05_FENCE_AFTER();
            if (elect_one_pred()) {
                int idx = 0;
#pragma unroll
                for (int term = 0; term < 3; term++) {
                    uint32_t ab = tb + ((term == 2) ? 96u : 0u);
                    uint64_t bd = (term == 1) ? descL : descH;
#pragma unroll
                    for (int k = 0; k < 12; k++) {
                        uint64_t d = bd + (uint64_t)((k >> 2) * 1280 + (k & 3) * 2);
                        TCGEN05_MMA_F16(dcol, ab + (uint32_t)(k * 8), d, IDESC_MAIN, idx > 0);
                        idx++;
                    }
                }
                TCGEN05_COMMIT(mb);
            }
        }
        if (prev >= 0) epilogue(tb + 192u + (uint32_t)prevbuf * 160u, prev, t, dx, y);
        prev = tile;
        prevbuf = buf;
        buf ^= 1;
    }
    if (prev >= 0) {
        MBARRIER_WAIT_PARITY(mb, parity); parity ^= 1;
        TCGEN05_FENCE_AFTER();
        epilogue(tb + 192u + (uint32_t)prevbuf * 160u, prev, t, dx, y);
    }
    __syncthreads();
    if (t < 32) TCGEN05_DEALLOC(tb, 512);
#else
    // Generic-PTX fallback (never executed on GB300: sm_103a SASS is loaded).
    int t = threadIdx.x;
    for (int tile = blockIdx.x; tile < ntiles; tile += gridDim.x) {
        size_t s = (size_t)tile * 128 + t;
        const float* xr = &x[s * 128];
        const float* ur = &u[s * 64];
        for (int o = 0; o < 128; o++) {
            float acc = 0.f;
            for (int k = 0; k < 128; k++) acc += xr[k] * g_A[o * 128 + k];
            for (int k = 0; k < 64; k++)  acc += ur[k] * g_B[o * 64 + k];
            dx[s * 128 + o] = acc;
        }
        for (int o = 0; o < 32; o++) {
            float acc = 0.f;
            for (int k = 0; k < 128; k++) acc += xr[k] * g_C[o * 128 + k];
            y[s * 32 + o] = acc;
        }
    }
#endif
}

// ---------------- launcher ----------------
extern "C" void kernel_launch(void* const* d_in, const int* in_sizes, int n_in,
                              void* d_out, int out_size) {
    const float* u = (const float*)d_in[0];
    const float* x = (const float*)d_in[1];
    const float* Q = (const float*)d_in[2];
    const float* P = (const float*)d_in[3];
    const float* S = (const float*)d_in[4];
    const float* G = (const float*)d_in[5];
    const float* H = (const float*)d_in[6];
    int N = in_sizes[0] / 64;
    float* dx = (float*)d_out;
    float* y = dx + (size_t)N * 128;

    k_prep1<<<80, 256>>>(Q, S, G, H);
    k_spec<<<1, 64>>>(Q);
    k_init<<<112, 256>>>(P, G, Q);
    k_ns_fused<<<NSGRID, 256>>>();
    k_B<<<32, 256>>>(H);
    k_packW<<<120, 256>>>();

    int smem = 1024 + W_IMG_BYTES + 64;
    cudaFuncSetAttribute(k_main, cudaFuncAttributeMaxDynamicSharedMemorySize, smem);
    int ntiles = N / 128;
    k_main<<<152, 128, smem>>>(x, u, dx, y, ntiles);
}

// round 7
// speedup vs baseline: 6.7020x; 1.0353x over previous
#include <cuda_runtime.h>
#include <cuda_bf16.h>
#include <math.h>
#include <stdint.h>

#define NS_ITERS 16
#define LAN_M 56
#define EPSc 1e-4f
#define NSGRID 128
#define IDESC_MAIN 0x8280490u   // f32 accum, bf16 a/b, M=128, N=160
#define W_IMG_HALF 61440
#define W_IMG_BYTES 122880

#if !defined(__CUDA_ARCH__) || defined(__CUDA_ARCH_FEAT_SM103_ALL) || defined(__CUDA_ARCH_FEAT_SM100_ALL)
#define TC_OK 1
#else
#define TC_OK 0
#endif

// ---------------- PTX helpers ----------------
__device__ __forceinline__ uint32_t smem_u32(const void* p) {
    uint32_t a;
    asm("{ .reg .u64 t; cvta.to.shared.u64 t, %1; cvt.u32.u64 %0, t; }" : "=r"(a) : "l"(p));
    return a;
}
__device__ __forceinline__ uint32_t elect_one_pred() {
    uint32_t pred;
    asm volatile("{\n\t.reg .pred p;\n\telect.sync _|p, 0xFFFFFFFF;\n\tselp.b32 %0, 1, 0, p;\n\t}" : "=r"(pred));
    return pred;
}
#define TCGEN05_ALLOC(a, n) asm volatile("tcgen05.alloc.cta_group::1.sync.aligned.shared::cta.b32 [%0], %1;" :: "r"((uint32_t)(a)), "r"((uint32_t)(n)) : "memory")
#define TCGEN05_DEALLOC(a, n) asm volatile("tcgen05.dealloc.cta_group::1.sync.aligned.b32 %0, %1;" :: "r"(a), "r"((uint32_t)(n)))
#define TCGEN05_RELINQ() asm volatile("tcgen05.relinquish_alloc_permit.cta_group::1.sync.aligned;")
#define TCGEN05_WAIT_ST() asm volatile("tcgen05.wait::st.sync.aligned;" ::: "memory")
#define TCGEN05_WAIT_LD() asm volatile("tcgen05.wait::ld.sync.aligned;" ::: "memory")
#define TCGEN05_FENCE_BEFORE() asm volatile("tcgen05.fence::before_thread_sync;" ::: "memory")
#define TCGEN05_FENCE_AFTER()  asm volatile("tcgen05.fence::after_thread_sync;" ::: "memory")
#define TCGEN05_COMMIT(m) asm volatile("tcgen05.commit.cta_group::1.mbarrier::arrive::one.shared::cluster.b64 [%0];" :: "r"((uint32_t)(m)) : "memory")
#define MBARRIER_INIT(m, c) asm volatile("mbarrier.init.shared.b64 [%0], %1;" :: "r"((uint32_t)(m)), "r"((uint32_t)(c)) : "memory")
#define MBARRIER_WAIT_PARITY(m, ph) do { \
    uint32_t _m = (uint32_t)(m), _p = (uint32_t)(ph), _d; \
    asm volatile("{\n\t.reg .pred p;\n\tmbarrier.try_wait.parity.acquire.cta.shared::cta.b64 p, [%1], %2;\n\tselp.b32 %0, 1, 0, p;\n\t}" : "=r"(_d) : "r"(_m), "r"(_p) : "memory"); \
    if (!_d) { asm volatile("{\n\t.reg .pred P1;\n\tWL_%=:\n\tmbarrier.try_wait.parity.acquire.cta.shared::cta.b64 P1, [%0], %1, 0x989680;\n\t@P1 bra.uni WD_%=;\n\tbra.uni WL_%=;\n\tWD_%=:\n\t}" :: "r"(_m), "r"(_p) : "memory"); } \
} while (0)
#define TCGEN05_MMA_F16(d, a, bd, id, en) do { \
    uint32_t _e = (en) ? 1 : 0, _z = 0; \
    asm volatile("{\n\t.reg .pred p;\n\tsetp.ne.u32 p, %6, 0;\n\ttcgen05.mma.cta_group::1.kind::f16 [%0], [%1], %2, %3, {%4, %4, %4, %4}, p;\n\t}" \
        :: "r"(d), "r"(a), "l"(bd), "r"(id), "r"(_z), "r"(_z), "r"(_e) : "memory"); \
} while (0)
#define TCGEN05_ST_X16(a, r) asm volatile("tcgen05.st.sync.aligned.32x32b.x16.b32 [%0], {%1,%2,%3,%4,%5,%6,%7,%8,%9,%10,%11,%12,%13,%14,%15,%16};" \
    :: "r"(a), "r"((r)[0]), "r"((r)[1]), "r"((r)[2]), "r"((r)[3]), "r"((r)[4]), "r"((r)[5]), "r"((r)[6]), "r"((r)[7]), \
       "r"((r)[8]), "r"((r)[9]), "r"((r)[10]), "r"((r)[11]), "r"((r)[12]), "r"((r)[13]), "r"((r)[14]), "r"((r)[15]) : "memory")
#define TCGEN05_LD_X32(r, a) asm volatile("tcgen05.ld.sync.aligned.32x32b.x32.b32 {%0,%1,%2,%3,%4,%5,%6,%7,%8,%9,%10,%11,%12,%13,%14,%15,%16,%17,%18,%19,%20,%21,%22,%23,%24,%25,%26,%27,%28,%29,%30,%31}, [%32];" \
    : "=r"((r)[0]), "=r"((r)[1]), "=r"((r)[2]), "=r"((r)[3]), "=r"((r)[4]), "=r"((r)[5]), "=r"((r)[6]), "=r"((r)[7]), \
      "=r"((r)[8]), "=r"((r)[9]), "=r"((r)[10]), "=r"((r)[11]), "=r"((r)[12]), "=r"((r)[13]), "=r"((r)[14]), "=r"((r)[15]), \
      "=r"((r)[16]), "=r"((r)[17]), "=r"((r)[18]), "=r"((r)[19]), "=r"((r)[20]), "=r"((r)[21]), "=r"((r)[22]), "=r"((r)[23]), \
      "=r"((r)[24]), "=r"((r)[25]), "=r"((r)[26]), "=r"((r)[27]), "=r"((r)[28]), "=r"((r)[29]), "=r"((r)[30]), "=r"((r)[31]) : "r"(a))
static __device__ __forceinline__ uint64_t make_desc(uint32_t addr) {
    return ((uint64_t)2 << 61) | ((uint64_t)1 << 46) | ((uint64_t)64 << 32) | ((uint64_t)1 << 16)
         | ((uint64_t)(addr >> 4) & 0x3FFF);
}

// ---------------- device scratch ----------------
__device__ __align__(16) float g_HtH[64 * 64];
__device__ __align__(16) float g_A0[128 * 128];
__device__ __align__(16) float g_A[128 * 128];
__device__ __align__(16) float g_C[32 * 128];
__device__ __align__(16) float g_Ybuf[2][128 * 128];
__device__ __align__(16) float g_Zbuf[2][128 * 128];
__device__ __align__(16) float g_T[128 * 128];
__device__ float g_scal[2];
__device__ unsigned g_cnt;
__device__ __align__(16) unsigned char g_Wimg[W_IMG_BYTES];

// ---------------- setup: HtH + A0 ----------------
__global__ void k_prep1(const float* __restrict__ Q, const float* __restrict__ S,
                        const float* __restrict__ G, const float* __restrict__ H) {
    int b = blockIdx.x, t = threadIdx.x;
    if (b < 16) {
        int e = b * 256 + t, i = e >> 6, j = e & 63;
        float s = 0.f;
#pragma unroll 8
        for (int k = 0; k < 128; k++) s += H[k * 64 + i] * H[k * 64 + j];
        g_HtH[e] = s;
    } else {
        int e = (b - 16) * 256 + t, i = e >> 7, j = e & 127;
        float s = 0.f;
#pragma unroll
        for (int k = 0; k < 32; k++) s += G[k * 128 + i] * G[k * 128 + j];
        g_A0[e] = -0.5f * (Q[e] + s + ((i == j) ? EPSc : 0.f)) + S[e];
    }
}

// ---------------- spectral: ||Q||_F + Lanczos lam_max(HtH) + multisection ----------------
__global__ void k_spec(const float* __restrict__ Qm) {
    __shared__ float sM[64 * 64], v[64], vp[64], red[64], al[LAN_M], be[LAN_M + 1];
    __shared__ float slo, shi;
    __shared__ int sflag[64];
    int t = threadIdx.x;
    for (int i = t; i < 4096; i += 64) sM[i] = g_HtH[i];
    float s = 0.f;
    for (int i = t; i < 16384; i += 64) { float q = Qm[i]; s += q * q; }
    red[t] = s; __syncthreads();
    for (int o = 32; o > 0; o >>= 1) { if (t < o) red[t] += red[t + o]; __syncthreads(); }
    float cfro = sqrtf(red[0]); __syncthreads();
    float rs = 0.f;
    for (int k = 0; k < 64; k++) rs += sM[t * 64 + k];
    red[t] = rs * rs; __syncthreads();
    for (int o = 32; o > 0; o >>= 1) { if (t < o) red[t] += red[t + o]; __syncthreads(); }
    float n0 = sqrtf(red[0]); __syncthreads();
    v[t] = rs / n0; vp[t] = 0.f;
    if (t == 0) be[0] = 0.f;
    __syncthreads();
    for (int j = 0; j < LAN_M; j++) {
        float acc = 0.f;
#pragma unroll 8
        for (int k = 0; k < 64; k++) acc += sM[t * 64 + k] * v[k];
        float wi = acc - be[j] * vp[t];
        red[t] = wi * v[t]; __syncthreads();
        for (int o = 32; o > 0; o >>= 1) { if (t < o) red[t] += red[t + o]; __syncthreads(); }
        float a = red[0]; __syncthreads();
        if (t == 0) al[j] = a;
        wi -= a * v[t];
        red[t] = wi * wi; __syncthreads();
        for (int o = 32; o > 0; o >>= 1) { if (t < o) red[t] += red[t + o]; __syncthreads(); }
        float bn = sqrtf(red[0]); __syncthreads();
        if (t == 0) be[j + 1] = bn;
        vp[t] = v[t];
        v[t] = (bn > 1e-12f) ? (wi / bn) : 0.f;
        __syncthreads();
    }
    if (t == 0) {
        float hi = 0.f;
        for (int j = 0; j < LAN_M; j++) {
            float g = al[j] + fabsf(be[j]) + fabsf(be[j + 1]);
            if (g > hi) hi = g;
        }
        slo = 0.f; shi = hi + 1.f;
    }
    __syncthreads();
    for (int r = 0; r < 5; r++) {
        float lo = slo, hi = shi;
        float xm = lo + (hi - lo) * (float)(t + 1) * (1.f / 65.f);
        int cnt = 0; float d = 1.f;
        for (int j = 0; j < LAN_M; j++) {
            float bj = (j == 0) ? 0.f : be[j];
            d = (al[j] - xm) - __fdividef(bj * bj, d);
            if (d == 0.f) d = -1e-30f;
            if (d < 0.f) cnt++;
        }
        sflag[t] = (cnt >= LAN_M) ? 1 : 0;
        __syncthreads();
        if (t == 0) {
            float nlo = lo, nhi = hi;
            for (int q = 0; q < 64; q++) {
                float sq = lo + (hi - lo) * (float)(q + 1) * (1.f / 65.f);
                if (sflag[q]) { nhi = sq; break; }
                nlo = sq;
            }
            slo = nlo; shi = nhi;
        }
        __syncthreads();
    }
    if (t == 0) {
        float lam = 0.5f * (slo + shi);
        if (lam < 1e-20f) lam = 1e-20f;
        g_scal[0] = 1.0f / cfro;
        g_scal[1] = sqrtf(cfro) / (1.01f * sqrtf(lam));
    }
}

// ---------------- init: A = A0@P ; C = G@P ; Y0 = Q/c ; Z0 = I ; reset barrier ----------------
__global__ void k_init(const float* __restrict__ P, const float* __restrict__ G,
                       const float* __restrict__ Qm) {
    int b = blockIdx.x, t = threadIdx.x;
    if (b == 0 && t == 0) g_cnt = 0u;
    if (b < 64) {
        int e = b * 256 + t, i = e >> 7, j = e & 127;
        const float* a0 = &g_A0[i * 128];
        float s = 0.f;
#pragma unroll 8
        for (int k = 0; k < 128; k++) s += a0[k] * P[k * 128 + j];
        g_A[e] = s;
    } else if (b < 80) {
        int e = (b - 64) * 256 + t, i = e >> 7, j = e & 127;
        const float* gi = &G[i * 128];
        float s = 0.f;
#pragma unroll 8
        for (int k = 0; k < 128; k++) s += gi[k] * P[k * 128 + j];
        g_C[e] = s;
    } else {
        float ic = g_scal[0];
        int base = (b - 80) * 1024 + t;
#pragma unroll
        for (int r = 0; r < 4; r++) {
            int idx = base + r * 256;
            if (idx < 16384) g_Ybuf[0][idx] = Qm[idx] * ic;
            else { int e2 = idx - 16384; g_Zbuf[0][e2] = ((e2 >> 7) == (e2 & 127)) ? 1.f : 0.f; }
        }
    }
}

// ---------------- fused Newton-Schulz: SMEM-staged operand, grid spin barrier ----------------
__device__ __forceinline__ void gridbar(unsigned target) {
    __syncthreads();
    if (threadIdx.x == 0) {
        __threadfence();
        atomicAdd(&g_cnt, 1u);
        while (*((volatile unsigned*)&g_cnt) < target) { }
        __threadfence();
    }
    __syncthreads();
}

__global__ void __launch_bounds__(256, 1) k_ns_fused() {
    extern __shared__ float sS[];          // 16384 floats: staged 128x128 operand
    __shared__ float rowbuf[2][128];
    int b = blockIdx.x, t = threadIdx.x;
    int p = 0;
    unsigned nb = 0;
    for (int it = 0; it < NS_ITERS; it++) {
        const float* Y = g_Ybuf[p];
        const float* Z = g_Zbuf[p];
        float* Yn = g_Ybuf[p ^ 1];
        float* Zn = g_Zbuf[p ^ 1];
        if (b < 64) {                       // T = 1.5I - 0.5 Z@Y : stage Y
            for (int i = t; i < 4096; i += 256)
                ((float4*)sS)[i] = __ldcg(((const float4*)Y) + i);
            int i0 = b * 2;
            rowbuf[t >> 7][t & 127] = __ldcg(&Z[i0 * 128 + t]);
            __syncthreads();
            int i = t >> 7, j = t & 127;
            const float* rw = rowbuf[i];
            float s = 0.f;
#pragma unroll 8
            for (int k = 0; k < 128; k++) s += rw[k] * sS[k * 128 + j];
            g_T[(i0 + i) * 128 + j] = (((i0 + i) == j) ? 1.5f : 0.f) - 0.5f * s;
        } else {                            // pre-stage Z for phase 2
            for (int i = t; i < 4096; i += 256)
                ((float4*)sS)[i] = __ldcg(((const float4*)Z) + i);
        }
        nb++; gridbar(nb * NSGRID);
        if (b < 64) {                       // Yn = Y@T : stage T
            for (int i = t; i < 4096; i += 256)
                ((float4*)sS)[i] = __ldcg(((const float4*)g_T) + i);
            int i0 = b * 2;
            rowbuf[t >> 7][t & 127] = __ldcg(&Y[i0 * 128 + t]);
            __syncthreads();
            int i = t >> 7, j = t & 127;
            const float* rw = rowbuf[i];
            float s = 0.f;
#pragma unroll 8
            for (int k = 0; k < 128; k++) s += rw[k] * sS[k * 128 + j];
            Yn[(i0 + i) * 128 + j] = s;
        } else {                            // Zn = T@Z : Z already staged
            int i0 = (b - 64) * 2;
            rowbuf[t >> 7][t & 127] = __ldcg(&g_T[i0 * 128 + t]);
            __syncthreads();
            int i = t >> 7, j = t & 127;
            const float* rw = rowbuf[i];
            float s = 0.f;
#pragma unroll 8
            for (int k = 0; k < 128; k++) s += rw[k] * sS[k * 128 + j];
            Zn[(i0 + i) * 128 + j] = s;
        }
        nb++; gridbar(nb * NSGRID);
        __syncthreads();                    // protect sS re-stage next iter
        p ^= 1;
    }
}

// ---------------- pack W (computes B inline): SW128-swizzled bf16 hi/lo image ----------------
__global__ void k_packW(const float* __restrict__ H) {
    int idx = blockIdx.x * 256 + threadIdx.x;     // 120 x 256 = 30720 = 160*192
    int o = idx / 192, k = idx % 192;
    float v;
    if (k < 128) {
        v = (o < 128) ? g_A[o * 128 + k] : g_C[(o - 128) * 128 + k];
    } else if (o < 128) {                          // B[o][k-128] = scal1 * Yf[o,:] . H[:,k-128]
        const float* yr = &g_Ybuf[0][o * 128];
        int j = k - 128;
        float s = 0.f;
#pragma unroll 8
        for (int kk = 0; kk < 128; kk++) s += yr[kk] * H[kk * 64 + j];
        v = s * g_scal[1];
    } else {
        v = 0.f;
    }
    __nv_bfloat16 h = __float2bfloat16_rn(v);
    __nv_bfloat16 l = __float2bfloat16_rn(v - __bfloat162float(h));
    uint32_t boff = (uint32_t)(((o >> 3) + (k >> 6) * 20) * 1024 + (o & 7) * 128 + (k & 63) * 2);
    uint32_t sw = boff ^ ((boff >> 3) & 0x70);
    *(unsigned short*)(g_Wimg + sw) = __bfloat16_as_ushort(h);
    *(unsigned short*)(g_Wimg + W_IMG_HALF + sw) = __bfloat16_as_ushort(l);
}

// ---------------- main GEMM: tcgen05 bf16 split, 256 threads, persistent CTAs ----------------
__device__ __forceinline__ uint32_t packhi2(float a, float b) {
    __nv_bfloat16 ha = __float2bfloat16_rn(a), hb = __float2bfloat16_rn(b);
    return (uint32_t)__bfloat16_as_ushort(ha) | ((uint32_t)__bfloat16_as_ushort(hb) << 16);
}
__device__ __forceinline__ uint32_t packlo2(float a, float b) {
    __nv_bfloat16 ha = __float2bfloat16_rn(a), hb = __float2bfloat16_rn(b);
    float ra = a - __bfloat162float(ha), rb = b - __bfloat162float(hb);
    __nv_bfloat16 la = __float2bfloat16_rn(ra), lb = __float2bfloat16_rn(rb);
    return (uint32_t)__bfloat16_as_ushort(la) | ((uint32_t)__bfloat16_as_ushort(lb) << 16);
}

__global__ void __launch_bounds__(256, 1) k_main(
    const float* __restrict__ x, const float* __restrict__ u,
    float* __restrict__ dx, float* __restrict__ y, int ntiles) {
#if TC_OK
    extern __shared__ unsigned char smraw[];
    __shared__ uint32_t s_tptr;
    __shared__ __align__(8) unsigned long long s_mbar;
    int t = threadIdx.x;
    int wid = t >> 5;
    int sub = wid & 3;                 // TMEM subpartition
    int lane = t & 31;
    int row = sub * 32 + lane;         // tile row this thread owns (0..127)
    bool hiGrp = wid < 4;              // warps 0-3: hi cols; warps 4-7: lo cols
    uint32_t smbase = smem_u32(smraw);
    uint32_t wbase = (smbase + 1023u) & ~1023u;
    unsigned char* wptr = smraw + (wbase - smbase);
    {   // copy pre-swizzled W image (hi+lo) to smem
        const float4* src = (const float4*)g_Wimg;
        float4* dst = (float4*)wptr;
        for (int i = t; i < W_IMG_BYTES / 16; i += 256) dst[i] = src[i];
    }
    if (t < 32) { TCGEN05_ALLOC(smem_u32(&s_tptr), 512); TCGEN05_RELINQ(); }
    if (t == 0) MBARRIER_INIT(smem_u32(&s_mbar), 1);
    __syncthreads();
    uint32_t tb = s_tptr;
    uint32_t mb = smem_u32(&s_mbar);
    uint64_t descH = make_desc(wbase);
    uint64_t descL = make_desc(wbase + W_IMG_HALF);
    uint32_t wofs = (uint32_t)sub << 21;
    uint32_t parity = 0;
    int prev = -1;
    int buf = 0, prevbuf = 0;

    for (int tile = blockIdx.x; tile < ntiles; tile += gridDim.x) {
        size_t sbase = (size_t)tile * 128;
        const float* xr = &x[(sbase + row) * 128];
        const float* ur = &u[(sbase + row) * 64];
        if (prev >= 0) { MBARRIER_WAIT_PARITY(mb, parity); parity ^= 1; TCGEN05_FENCE_AFTER(); }
        // convert 192 fp32 of this row -> bf16; hi warps write TMEM cols 0..95, lo warps 96..191
#pragma unroll
        for (int c = 0; c < 6; c++) {
            const float4* s4 = (c < 4) ? (const float4*)(xr + 32 * c) : (const float4*)(ur + 32 * (c - 4));
            float4 v[8];
#pragma unroll
            for (int q = 0; q < 8; q++) v[q] = s4[q];
            uint32_t pk[16];
            if (hiGrp) {
#pragma unroll
                for (int q = 0; q < 8; q++) {
                    pk[2 * q]     = packhi2(v[q].x, v[q].y);
                    pk[2 * q + 1] = packhi2(v[q].z, v[q].w);
                }
                TCGEN05_ST_X16(tb + (uint32_t)(c * 16) + wofs, pk);
            } else {
#pragma unroll
                for (int q = 0; q < 8; q++) {
                    pk[2 * q]     = packlo2(v[q].x, v[q].y);
                    pk[2 * q + 1] = packlo2(v[q].z, v[q].w);
                }
                TCGEN05_ST_X16(tb + (uint32_t)(96 + c * 16) + wofs, pk);
            }
        }
        TCGEN05_WAIT_ST();
        TCGEN05_FENCE_BEFORE();
        __syncthreads();
        uint32_t dcol = tb + 192u + (uint32_t)buf * 160u;
        if (t < 32) {
            TCGEN05_FENCE_AFTER();
            if (elect_one_pred()) {
                int idx = 0;
#pragma unroll
                for (int term = 0; term < 3; term++) {
                    uint32_t ab = tb + ((term == 2) ? 96u : 0u);
                    uint64_t bd = (term == 1) ? descL : descH;
#pragma unroll
                    for (int k = 0; k < 12; k++) {
                        uint64_t d = bd + (uint64_t)((k >> 2) * 1280 + (k & 3) * 2);
                        TCGEN05_MMA_F16(dcol, ab + (uint32_t)(k * 8), d, IDESC_MAIN, idx > 0);
                        idx++;
                    }
                }
                TCGEN05_COMMIT(mb);
            }
        }
        if (prev >= 0) {   // epilogue of prev tile, col-split across 8 warps, overlaps MMA
            uint32_t pd = tb + 192u + (uint32_t)prevbuf * 160u;
            size_t srow = (size_t)prev * 128 + row;
            uint32_t r[32];
            if (hiGrp) {
#pragma unroll
                for (int g = 0; g < 3; g++) {        // dx cols 0..95
                    TCGEN05_LD_X32(r, pd + g * 32);
                    TCGEN05_WAIT_LD();
                    float4* dst = (float4*)&dx[srow * 128 + g * 32];
#pragma unroll
                    for (int q = 0; q < 8; q++)
                        dst[q] = make_float4(__uint_as_float(r[4 * q]), __uint_as_float(r[4 * q + 1]),
                                             __uint_as_float(r[4 * q + 2]), __uint_as_float(r[4 * q + 3]));
                }
            } else {
                TCGEN05_LD_X32(r, pd + 96);          // dx cols 96..127
                TCGEN05_WAIT_LD();
                float4* dst = (float4*)&dx[srow * 128 + 96];
#pragma unroll
                for (int q = 0; q < 8; q++)
                    dst[q] = make_float4(__uint_as_float(r[4 * q]), __uint_as_float(r[4 * q + 1]),
                                         __uint_as_float(r[4 * q + 2]), __uint_as_float(r[4 * q + 3]));
                TCGEN05_LD_X32(r, pd + 128);         // y cols 0..31
                TCGEN05_WAIT_LD();
                float4* dy = (float4*)&y[srow * 32];
#pragma unroll
                for (int q = 0; q < 8; q++)
                    dy[q] = make_float4(__uint_as_float(r[4 * q]), __uint_as_float(r[4 * q + 1]),
                                        __uint_as_float(r[4 * q + 2]), __uint_as_float(r[4 * q + 3]));
            }
            TCGEN05_FENCE_BEFORE();
        }
        prev = tile;
        prevbuf = buf;
        buf ^= 1;
    }
    if (prev >= 0) {
        MBARRIER_WAIT_PARITY(mb, parity); parity ^= 1;
        TCGEN05_FENCE_AFTER();
        uint32_t pd = tb + 192u + (uint32_t)prevbuf * 160u;
        size_t srow = (size_t)prev * 128 + row;
        uint32_t r[32];
        if (hiGrp) {
#pragma unroll
            for (int g = 0; g < 3; g++) {
                TCGEN05_LD_X32(r, pd + g * 32);
                TCGEN05_WAIT_LD();
                float4* dst = (float4*)&dx[srow * 128 + g * 32];
#pragma unroll
                for (int q = 0; q < 8; q++)
                    dst[q] = make_float4(__uint_as_float(r[4 * q]), __uint_as_float(r[4 * q + 1]),
                                         __uint_as_float(r[4 * q + 2]), __uint_as_float(r[4 * q + 3]));
            }
        } else {
            TCGEN05_LD_X32(r, pd + 96);
            TCGEN05_WAIT_LD();
            float4* dst = (float4*)&dx[srow * 128 + 96];
#pragma unroll
            for (int q = 0; q < 8; q++)
                dst[q] = make_float4(__uint_as_float(r[4 * q]), __uint_as_float(r[4 * q + 1]),
                                     __uint_as_float(r[4 * q + 2]), __uint_as_float(r[4 * q + 3]));
            TCGEN05_LD_X32(r, pd + 128);
            TCGEN05_WAIT_LD();
            float4* dy = (float4*)&y[srow * 32];
#pragma unroll
            for (int q = 0; q < 8; q++)
                dy[q] = make_float4(__uint_as_float(r[4 * q]), __uint_as_float(r[4 * q + 1]),
                                    __uint_as_float(r[4 * q + 2]), __uint_as_float(r[4 * q + 3]));
        }
        TCGEN05_FENCE_BEFORE();
    }
    __syncthreads();
    if (t < 32) TCGEN05_DEALLOC(tb, 512);
#else
    // Generic-PTX fallback (never executed on GB300: sm_103a SASS is loaded).
    int t = threadIdx.x;
    for (int tile = blockIdx.x; tile < ntiles; tile += gridDim.x) {
        for (int rr = t; rr < 128; rr += blockDim.x) {
            size_t s = (size_t)tile * 128 + rr;
            const float* xr = &x[s * 128];
            const float* ur = &u[s * 64];
            for (int o = 0; o < 128; o++) {
                float acc = 0.f;
                for (int k = 0; k < 128; k++) acc += xr[k] * g_A[o * 128 + k];
                for (int k = 0; k < 64; k++)  acc += ur[k] * g_A[0] * 0.f;  // placeholder
                dx[s * 128 + o] = acc;
            }
            for (int o = 0; o < 32; o++) {
                float acc = 0.f;
                for (int k = 0; k < 128; k++) acc += xr[k] * g_C[o * 128 + k];
                y[s * 32 + o] = acc;
            }
        }
    }
#endif
}

// ---------------- launcher ----------------
extern "C" void kernel_launch(void* const* d_in, const int* in_sizes, int n_in,
                              void* d_out, int out_size) {
    const float* u = (const float*)d_in[0];
    const float* x = (const float*)d_in[1];
    const float* Q = (const float*)d_in[2];
    const float* P = (const float*)d_in[3];
    const float* S = (const float*)d_in[4];
    const float* G = (const float*)d_in[5];
    const float* H = (const float*)d_in[6];
    int N = in_sizes[0] / 64;
    float* dx = (float*)d_out;
    float* y = dx + (size_t)N * 128;

    k_prep1<<<80, 256>>>(Q, S, G, H);
    k_spec<<<1, 64>>>(Q);
    k_init<<<112, 256>>>(P, G, Q);

    int ns_smem = 16384 * sizeof(float);
    cudaFuncSetAttribute(k_ns_fused, cudaFuncAttributeMaxDynamicSharedMemorySize, ns_smem);
    k_ns_fused<<<NSGRID, 256, ns_smem>>>();

    k_packW<<<120, 256>>>(H);

    int smem = 1024 + W_IMG_BYTES + 64;
    cudaFuncSetAttribute(k_main, cudaFuncAttributeMaxDynamicSharedMemorySize, smem);
    int ntiles = N / 128;
    k_main<<<152, 256, smem>>>(x, u, dx, y, ntiles);
}

// round 8
// speedup vs baseline: 6.7502x; 1.0072x over previous
#include <cuda_runtime.h>
#include <cuda_bf16.h>
#include <math.h>
#include <stdint.h>

#define NS_ITERS 16
#define LAN_M 56
#define EPSc 1e-4f
#define NSGRID 128
#define IDESC_MAIN 0x8280490u   // f32 accum, bf16 a/b, M=128, N=160
#define W_IMG_HALF 61440
#define W_IMG_BYTES 122880
#define XS_F4 (128 * 33)        // x stage: 128 rows x 33 float4 (32 data + 1 pad)
#define US_F4 (128 * 17)        // u stage: 128 rows x 17 float4 (16 data + 1 pad)

#if !defined(__CUDA_ARCH__) || defined(__CUDA_ARCH_FEAT_SM103_ALL) || defined(__CUDA_ARCH_FEAT_SM100_ALL)
#define TC_OK 1
#else
#define TC_OK 0
#endif

// ---------------- PTX helpers ----------------
__device__ __forceinline__ uint32_t smem_u32(const void* p) {
    uint32_t a;
    asm("{ .reg .u64 t; cvta.to.shared.u64 t, %1; cvt.u32.u64 %0, t; }" : "=r"(a) : "l"(p));
    return a;
}
__device__ __forceinline__ uint32_t elect_one_pred() {
    uint32_t pred;
    asm volatile("{\n\t.reg .pred p;\n\telect.sync _|p, 0xFFFFFFFF;\n\tselp.b32 %0, 1, 0, p;\n\t}" : "=r"(pred));
    return pred;
}
#define TCGEN05_ALLOC(a, n) asm volatile("tcgen05.alloc.cta_group::1.sync.aligned.shared::cta.b32 [%0], %1;" :: "r"((uint32_t)(a)), "r"((uint32_t)(n)) : "memory")
#define TCGEN05_DEALLOC(a, n) asm volatile("tcgen05.dealloc.cta_group::1.sync.aligned.b32 %0, %1;" :: "r"(a), "r"((uint32_t)(n)))
#define TCGEN05_RELINQ() asm volatile("tcgen05.relinquish_alloc_permit.cta_group::1.sync.aligned;")
#define TCGEN05_WAIT_ST() asm volatile("tcgen05.wait::st.sync.aligned;" ::: "memory")
#define TCGEN05_WAIT_LD() asm volatile("tcgen05.wait::ld.sync.aligned;" ::: "memory")
#define TCGEN05_FENCE_BEFORE() asm volatile("tcgen05.fence::before_thread_sync;" ::: "memory")
#define TCGEN05_FENCE_AFTER()  asm volatile("tcgen05.fence::after_thread_sync;" ::: "memory")
#define TCGEN05_COMMIT(m) asm volatile("tcgen05.commit.cta_group::1.mbarrier::arrive::one.shared::cluster.b64 [%0];" :: "r"((uint32_t)(m)) : "memory")
#define MBARRIER_INIT(m, c) asm volatile("mbarrier.init.shared.b64 [%0], %1;" :: "r"((uint32_t)(m)), "r"((uint32_t)(c)) : "memory")
#define MBARRIER_WAIT_PARITY(m, ph) do { \
    uint32_t _m = (uint32_t)(m), _p = (uint32_t)(ph), _d; \
    asm volatile("{\n\t.reg .pred p;\n\tmbarrier.try_wait.parity.acquire.cta.shared::cta.b64 p, [%1], %2;\n\tselp.b32 %0, 1, 0, p;\n\t}" : "=r"(_d) : "r"(_m), "r"(_p) : "memory"); \
    if (!_d) { asm volatile("{\n\t.reg .pred P1;\n\tWL_%=:\n\tmbarrier.try_wait.parity.acquire.cta.shared::cta.b64 P1, [%0], %1, 0x989680;\n\t@P1 bra.uni WD_%=;\n\tbra.uni WL_%=;\n\tWD_%=:\n\t}" :: "r"(_m), "r"(_p) : "memory"); } \
} while (0)
#define TCGEN05_MMA_F16(d, a, bd, id, en) do { \
    uint32_t _e = (en) ? 1 : 0, _z = 0; \
    asm volatile("{\n\t.reg .pred p;\n\tsetp.ne.u32 p, %6, 0;\n\ttcgen05.mma.cta_group::1.kind::f16 [%0], [%1], %2, %3, {%4, %4, %4, %4}, p;\n\t}" \
        :: "r"(d), "r"(a), "l"(bd), "r"(id), "r"(_z), "r"(_z), "r"(_e) : "memory"); \
} while (0)
#define TCGEN05_ST_X16(a, r) asm volatile("tcgen05.st.sync.aligned.32x32b.x16.b32 [%0], {%1,%2,%3,%4,%5,%6,%7,%8,%9,%10,%11,%12,%13,%14,%15,%16};" \
    :: "r"(a), "r"((r)[0]), "r"((r)[1]), "r"((r)[2]), "r"((r)[3]), "r"((r)[4]), "r"((r)[5]), "r"((r)[6]), "r"((r)[7]), \
       "r"((r)[8]), "r"((r)[9]), "r"((r)[10]), "r"((r)[11]), "r"((r)[12]), "r"((r)[13]), "r"((r)[14]), "r"((r)[15]) : "memory")
#define TCGEN05_LD_X32(r, a) asm volatile("tcgen05.ld.sync.aligned.32x32b.x32.b32 {%0,%1,%2,%3,%4,%5,%6,%7,%8,%9,%10,%11,%12,%13,%14,%15,%16,%17,%18,%19,%20,%21,%22,%23,%24,%25,%26,%27,%28,%29,%30,%31}, [%32];" \
    : "=r"((r)[0]), "=r"((r)[1]), "=r"((r)[2]), "=r"((r)[3]), "=r"((r)[4]), "=r"((r)[5]), "=r"((r)[6]), "=r"((r)[7]), \
      "=r"((r)[8]), "=r"((r)[9]), "=r"((r)[10]), "=r"((r)[11]), "=r"((r)[12]), "=r"((r)[13]), "=r"((r)[14]), "=r"((r)[15]), \
      "=r"((r)[16]), "=r"((r)[17]), "=r"((r)[18]), "=r"((r)[19]), "=r"((r)[20]), "=r"((r)[21]), "=r"((r)[22]), "=r"((r)[23]), \
      "=r"((r)[24]), "=r"((r)[25]), "=r"((r)[26]), "=r"((r)[27]), "=r"((r)[28]), "=r"((r)[29]), "=r"((r)[30]), "=r"((r)[31]) : "r"(a))
static __device__ __forceinline__ uint64_t make_desc(uint32_t addr) {
    return ((uint64_t)2 << 61) | ((uint64_t)1 << 46) | ((uint64_t)64 << 32) | ((uint64_t)1 << 16)
         | ((uint64_t)(addr >> 4) & 0x3FFF);
}

// ---------------- device scratch ----------------
__device__ __align__(16) float g_HtH[64 * 64];
__device__ __align__(16) float g_A0[128 * 128];
__device__ __align__(16) float g_A[128 * 128];
__device__ __align__(16) float g_C[32 * 128];
__device__ __align__(16) float g_Ybuf[2][128 * 128];
__device__ __align__(16) float g_Zbuf[2][128 * 128];
__device__ __align__(16) float g_T[128 * 128];
__device__ float g_scal[2];
__device__ unsigned g_cnt;
__device__ __align__(16) unsigned char g_Wimg[W_IMG_BYTES];

// ---------------- setup: HtH + A0 ----------------
__global__ void k_prep1(const float* __restrict__ Q, const float* __restrict__ S,
                        const float* __restrict__ G, const float* __restrict__ H) {
    int b = blockIdx.x, t = threadIdx.x;
    if (b < 16) {
        int e = b * 256 + t, i = e >> 6, j = e & 63;
        float s = 0.f;
#pragma unroll 8
        for (int k = 0; k < 128; k++) s += H[k * 64 + i] * H[k * 64 + j];
        g_HtH[e] = s;
    } else {
        int e = (b - 16) * 256 + t, i = e >> 7, j = e & 127;
        float s = 0.f;
#pragma unroll
        for (int k = 0; k < 32; k++) s += G[k * 128 + i] * G[k * 128 + j];
        g_A0[e] = -0.5f * (Q[e] + s + ((i == j) ? EPSc : 0.f)) + S[e];
    }
}

// ---------------- spectral: ||Q||_F + Lanczos lam_max(HtH) + multisection ----------------
__global__ void k_spec(const float* __restrict__ Qm) {
    __shared__ float sM[64 * 64], v[64], vp[64], red[64], al[LAN_M], be[LAN_M + 1];
    __shared__ float slo, shi;
    __shared__ int sflag[64];
    int t = threadIdx.x;
    for (int i = t; i < 4096; i += 64) sM[i] = g_HtH[i];
    float s = 0.f;
    for (int i = t; i < 16384; i += 64) { float q = Qm[i]; s += q * q; }
    red[t] = s; __syncthreads();
    for (int o = 32; o > 0; o >>= 1) { if (t < o) red[t] += red[t + o]; __syncthreads(); }
    float cfro = sqrtf(red[0]); __syncthreads();
    float rs = 0.f;
    for (int k = 0; k < 64; k++) rs += sM[t * 64 + k];
    red[t] = rs * rs; __syncthreads();
    for (int o = 32; o > 0; o >>= 1) { if (t < o) red[t] += red[t + o]; __syncthreads(); }
    float n0 = sqrtf(red[0]); __syncthreads();
    v[t] = rs / n0; vp[t] = 0.f;
    if (t == 0) be[0] = 0.f;
    __syncthreads();
    for (int j = 0; j < LAN_M; j++) {
        float acc = 0.f;
#pragma unroll 8
        for (int k = 0; k < 64; k++) acc += sM[t * 64 + k] * v[k];
        float wi = acc - be[j] * vp[t];
        red[t] = wi * v[t]; __syncthreads();
        for (int o = 32; o > 0; o >>= 1) { if (t < o) red[t] += red[t + o]; __syncthreads(); }
        float a = red[0]; __syncthreads();
        if (t == 0) al[j] = a;
        wi -= a * v[t];
        red[t] = wi * wi; __syncthreads();
        for (int o = 32; o > 0; o >>= 1) { if (t < o) red[t] += red[t + o]; __syncthreads(); }
        float bn = sqrtf(red[0]); __syncthreads();
        if (t == 0) be[j + 1] = bn;
        vp[t] = v[t];
        v[t] = (bn > 1e-12f) ? (wi / bn) : 0.f;
        __syncthreads();
    }
    if (t == 0) {
        float hi = 0.f;
        for (int j = 0; j < LAN_M; j++) {
            float g = al[j] + fabsf(be[j]) + fabsf(be[j + 1]);
            if (g > hi) hi = g;
        }
        slo = 0.f; shi = hi + 1.f;
    }
    __syncthreads();
    for (int r = 0; r < 5; r++) {
        float lo = slo, hi = shi;
        float xm = lo + (hi - lo) * (float)(t + 1) * (1.f / 65.f);
        int cnt = 0; float d = 1.f;
        for (int j = 0; j < LAN_M; j++) {
            float bj = (j == 0) ? 0.f : be[j];
            d = (al[j] - xm) - __fdividef(bj * bj, d);
            if (d == 0.f) d = -1e-30f;
            if (d < 0.f) cnt++;
        }
        sflag[t] = (cnt >= LAN_M) ? 1 : 0;
        __syncthreads();
        if (t == 0) {
            float nlo = lo, nhi = hi;
            for (int q = 0; q < 64; q++) {
                float sq = lo + (hi - lo) * (float)(q + 1) * (1.f / 65.f);
                if (sflag[q]) { nhi = sq; break; }
                nlo = sq;
            }
            slo = nlo; shi = nhi;
        }
        __syncthreads();
    }
    if (t == 0) {
        float lam = 0.5f * (slo + shi);
        if (lam < 1e-20f) lam = 1e-20f;
        g_scal[0] = 1.0f / cfro;
        g_scal[1] = sqrtf(cfro) / (1.01f * sqrtf(lam));
    }
}

// ---------------- init: A = A0@P ; C = G@P ; Y0 = Q/c ; Z0 = I ; reset barrier ----------------
__global__ void k_init(const float* __restrict__ P, const float* __restrict__ G,
                       const float* __restrict__ Qm) {
    int b = blockIdx.x, t = threadIdx.x;
    if (b == 0 && t == 0) g_cnt = 0u;
    if (b < 64) {
        int e = b * 256 + t, i = e >> 7, j = e & 127;
        const float* a0 = &g_A0[i * 128];
        float s = 0.f;
#pragma unroll 8
        for (int k = 0; k < 128; k++) s += a0[k] * P[k * 128 + j];
        g_A[e] = s;
    } else if (b < 80) {
        int e = (b - 64) * 256 + t, i = e >> 7, j = e & 127;
        const float* gi = &G[i * 128];
        float s = 0.f;
#pragma unroll 8
        for (int k = 0; k < 128; k++) s += gi[k] * P[k * 128 + j];
        g_C[e] = s;
    } else {
        float ic = g_scal[0];
        int base = (b - 80) * 1024 + t;
#pragma unroll
        for (int r = 0; r < 4; r++) {
            int idx = base + r * 256;
            if (idx < 16384) g_Ybuf[0][idx] = Qm[idx] * ic;
            else { int e2 = idx - 16384; g_Zbuf[0][e2] = ((e2 >> 7) == (e2 & 127)) ? 1.f : 0.f; }
        }
    }
}

// ---------------- fused Newton-Schulz: SMEM-staged operand, grid spin barrier ----------------
__device__ __forceinline__ void gridbar(unsigned target) {
    __syncthreads();
    if (threadIdx.x == 0) {
        __threadfence();
        atomicAdd(&g_cnt, 1u);
        while (*((volatile unsigned*)&g_cnt) < target) { }
        __threadfence();
    }
    __syncthreads();
}

__global__ void __launch_bounds__(256, 1) k_ns_fused() {
    extern __shared__ float sS[];          // 16384 floats: staged 128x128 operand
    __shared__ float rowbuf[2][128];
    int b = blockIdx.x, t = threadIdx.x;
    int p = 0;
    unsigned nb = 0;
    for (int it = 0; it < NS_ITERS; it++) {
        const float* Y = g_Ybuf[p];
        const float* Z = g_Zbuf[p];
        float* Yn = g_Ybuf[p ^ 1];
        float* Zn = g_Zbuf[p ^ 1];
        if (b < 64) {                       // T = 1.5I - 0.5 Z@Y : stage Y
            for (int i = t; i < 4096; i += 256)
                ((float4*)sS)[i] = __ldcg(((const float4*)Y) + i);
            int i0 = b * 2;
            rowbuf[t >> 7][t & 127] = __ldcg(&Z[i0 * 128 + t]);
            __syncthreads();
            int i = t >> 7, j = t & 127;
            const float* rw = rowbuf[i];
            float s = 0.f;
#pragma unroll 8
            for (int k = 0; k < 128; k++) s += rw[k] * sS[k * 128 + j];
            g_T[(i0 + i) * 128 + j] = (((i0 + i) == j) ? 1.5f : 0.f) - 0.5f * s;
        } else {                            // pre-stage Z for phase 2
            for (int i = t; i < 4096; i += 256)
                ((float4*)sS)[i] = __ldcg(((const float4*)Z) + i);
        }
        nb++; gridbar(nb * NSGRID);
        if (b < 64) {                       // Yn = Y@T : stage T
            for (int i = t; i < 4096; i += 256)
                ((float4*)sS)[i] = __ldcg(((const float4*)g_T) + i);
            int i0 = b * 2;
            rowbuf[t >> 7][t & 127] = __ldcg(&Y[i0 * 128 + t]);
            __syncthreads();
            int i = t >> 7, j = t & 127;
            const float* rw = rowbuf[i];
            float s = 0.f;
#pragma unroll 8
            for (int k = 0; k < 128; k++) s += rw[k] * sS[k * 128 + j];
            Yn[(i0 + i) * 128 + j] = s;
        } else {                            // Zn = T@Z : Z already staged
            int i0 = (b - 64) * 2;
            rowbuf[t >> 7][t & 127] = __ldcg(&g_T[i0 * 128 + t]);
            __syncthreads();
            int i = t >> 7, j = t & 127;
            const float* rw = rowbuf[i];
            float s = 0.f;
#pragma unroll 8
            for (int k = 0; k < 128; k++) s += rw[k] * sS[k * 128 + j];
            Zn[(i0 + i) * 128 + j] = s;
        }
        nb++; gridbar(nb * NSGRID);
        __syncthreads();
        p ^= 1;
    }
}

// ---------------- pack W (computes B inline): SW128-swizzled bf16 hi/lo image ----------------
__global__ void k_packW(const float* __restrict__ H) {
    int idx = blockIdx.x * 256 + threadIdx.x;     // 120 x 256 = 30720 = 160*192
    int o = idx / 192, k = idx % 192;
    float v;
    if (k < 128) {
        v = (o < 128) ? g_A[o * 128 + k] : g_C[(o - 128) * 128 + k];
    } else if (o < 128) {
        const float* yr = &g_Ybuf[0][o * 128];
        int j = k - 128;
        float s = 0.f;
#pragma unroll 8
        for (int kk = 0; kk < 128; kk++) s += yr[kk] * H[kk * 64 + j];
        v = s * g_scal[1];
    } else {
        v = 0.f;
    }
    __nv_bfloat16 h = __float2bfloat16_rn(v);
    __nv_bfloat16 l = __float2bfloat16_rn(v - __bfloat162float(h));
    uint32_t boff = (uint32_t)(((o >> 3) + (k >> 6) * 20) * 1024 + (o & 7) * 128 + (k & 63) * 2);
    uint32_t sw = boff ^ ((boff >> 3) & 0x70);
    *(unsigned short*)(g_Wimg + sw) = __bfloat16_as_ushort(h);
    *(unsigned short*)(g_Wimg + W_IMG_HALF + sw) = __bfloat16_as_ushort(l);
}

// ---------------- main GEMM: tcgen05 bf16 split, coalesced SMEM staging ----------------
__device__ __forceinline__ uint32_t packhi2(float a, float b) {
    __nv_bfloat16 ha = __float2bfloat16_rn(a), hb = __float2bfloat16_rn(b);
    return (uint32_t)__bfloat16_as_ushort(ha) | ((uint32_t)__bfloat16_as_ushort(hb) << 16);
}
__device__ __forceinline__ uint32_t packlo2(float a, float b) {
    __nv_bfloat16 ha = __float2bfloat16_rn(a), hb = __float2bfloat16_rn(b);
    float ra = a - __bfloat162float(ha), rb = b - __bfloat162float(hb);
    __nv_bfloat16 la = __float2bfloat16_rn(ra), lb = __float2bfloat16_rn(rb);
    return (uint32_t)__bfloat16_as_ushort(la) | ((uint32_t)__bfloat16_as_ushort(lb) << 16);
}

__global__ void __launch_bounds__(256, 1) k_main(
    const float* __restrict__ x, const float* __restrict__ u,
    float* __restrict__ dx, float* __restrict__ y, int ntiles) {
#if TC_OK
    extern __shared__ unsigned char smraw[];
    __shared__ uint32_t s_tptr;
    __shared__ __align__(8) unsigned long long s_mbar;
    int t = threadIdx.x;
    int wid = t >> 5;
    int sub = wid & 3;
    int lane = t & 31;
    int row = sub * 32 + lane;
    bool hiGrp = wid < 4;
    uint32_t smbase = smem_u32(smraw);
    uint32_t wbase = (smbase + 1023u) & ~1023u;
    unsigned char* wptr = smraw + (wbase - smbase);
    float4* xs4 = (float4*)(wptr + W_IMG_BYTES);      // XS_F4 float4s
    float4* us4 = xs4 + XS_F4;                        // US_F4 float4s
    {
        const float4* src = (const float4*)g_Wimg;
        float4* dst = (float4*)wptr;
        for (int i = t; i < W_IMG_BYTES / 16; i += 256) dst[i] = src[i];
    }
    if (t < 32) { TCGEN05_ALLOC(smem_u32(&s_tptr), 512); TCGEN05_RELINQ(); }
    if (t == 0) MBARRIER_INIT(smem_u32(&s_mbar), 1);
    __syncthreads();
    uint32_t tb = s_tptr;
    uint32_t mb = smem_u32(&s_mbar);
    uint64_t descH = make_desc(wbase);
    uint64_t descL = make_desc(wbase + W_IMG_HALF);
    uint32_t wofs = (uint32_t)sub << 21;
    uint32_t parity = 0;
    int prev = -1;
    int buf = 0, prevbuf = 0;
    const float4* xg4 = (const float4*)x;
    const float4* ug4 = (const float4*)u;

    // prologue: stage first tile (coalesced)
    if (blockIdx.x < ntiles) {
        size_t sb = (size_t)blockIdx.x * 128;
        for (int i = t; i < 4096; i += 256) {
            int r = i >> 5, c4 = i & 31;
            xs4[r * 33 + c4] = xg4[((sb + r) << 5) + c4];
        }
        for (int i = t; i < 2048; i += 256) {
            int r = i >> 4, c4 = i & 15;
            us4[r * 17 + c4] = ug4[((sb + r) << 4) + c4];
        }
    }
    __syncthreads();

    for (int tile = blockIdx.x; tile < ntiles; tile += gridDim.x) {
        if (prev >= 0) { MBARRIER_WAIT_PARITY(mb, parity); parity ^= 1; TCGEN05_FENCE_AFTER(); }
        // convert this thread's row from SMEM -> TMEM bf16 (hi warps: cols 0..95, lo: 96..191)
        const float4* xr4 = xs4 + row * 33;
        const float4* ur4 = us4 + row * 17;
#pragma unroll
        for (int c = 0; c < 6; c++) {
            float4 v[8];
#pragma unroll
            for (int q = 0; q < 8; q++) v[q] = (c < 4) ? xr4[c * 8 + q] : ur4[(c - 4) * 8 + q];
            uint32_t pk[16];
            if (hiGrp) {
#pragma unroll
                for (int q = 0; q < 8; q++) {
                    pk[2 * q]     = packhi2(v[q].x, v[q].y);
                    pk[2 * q + 1] = packhi2(v[q].z, v[q].w);
                }
                TCGEN05_ST_X16(tb + (uint32_t)(c * 16) + wofs, pk);
            } else {
#pragma unroll
                for (int q = 0; q < 8; q++) {
                    pk[2 * q]     = packlo2(v[q].x, v[q].y);
                    pk[2 * q + 1] = packlo2(v[q].z, v[q].w);
                }
                TCGEN05_ST_X16(tb + (uint32_t)(96 + c * 16) + wofs, pk);
            }
        }
        TCGEN05_WAIT_ST();
        TCGEN05_FENCE_BEFORE();
        __syncthreads();                  // separates convert LDS from restage STS
        uint32_t dcol = tb + 192u + (uint32_t)buf * 160u;
        if (t < 32) {
            TCGEN05_FENCE_AFTER();
            if (elect_one_pred()) {
                int idx = 0;
#pragma unroll
                for (int term = 0; term < 3; term++) {
                    uint32_t ab = tb + ((term == 2) ? 96u : 0u);
                    uint64_t bd = (term == 1) ? descL : descH;
#pragma unroll
                    for (int k = 0; k < 12; k++) {
                        uint64_t d = bd + (uint64_t)((k >> 2) * 1280 + (k & 3) * 2);
                        TCGEN05_MMA_F16(dcol, ab + (uint32_t)(k * 8), d, IDESC_MAIN, idx > 0);
                        idx++;
                    }
                }
                TCGEN05_COMMIT(mb);
            }
        }
        if (prev >= 0) {   // epilogue of prev tile (overlaps MMA)
            uint32_t pd = tb + 192u + (uint32_t)prevbuf * 160u;
            size_t srow = (size_t)prev * 128 + row;
            uint32_t r[32];
            if (hiGrp) {
#pragma unroll
                for (int g = 0; g < 3; g++) {
                    TCGEN05_LD_X32(r, pd + g * 32);
                    TCGEN05_WAIT_LD();
                    float4* dst = (float4*)&dx[srow * 128 + g * 32];
#pragma unroll
                    for (int q = 0; q < 8; q++)
                        dst[q] = make_float4(__uint_as_float(r[4 * q]), __uint_as_float(r[4 * q + 1]),
                                             __uint_as_float(r[4 * q + 2]), __uint_as_float(r[4 * q + 3]));
                }
            } else {
                TCGEN05_LD_X32(r, pd + 96);
                TCGEN05_WAIT_LD();
                float4* dst = (float4*)&dx[srow * 128 + 96];
#pragma unroll
                for (int q = 0; q < 8; q++)
                    dst[q] = make_float4(__uint_as_float(r[4 * q]), __uint_as_float(r[4 * q + 1]),
                                         __uint_as_float(r[4 * q + 2]), __uint_as_float(r[4 * q + 3]));
                TCGEN05_LD_X32(r, pd + 128);
                TCGEN05_WAIT_LD();
                float4* dy = (float4*)&y[srow * 32];
#pragma unroll
                for (int q = 0; q < 8; q++)
                    dy[q] = make_float4(__uint_as_float(r[4 * q]), __uint_as_float(r[4 * q + 1]),
                                        __uint_as_float(r[4 * q + 2]), __uint_as_float(r[4 * q + 3]));
            }
            TCGEN05_FENCE_BEFORE();
        }
        // stage next tile (overlaps MMA)
        int nxt = tile + gridDim.x;
        if (nxt < ntiles) {
            size_t sb = (size_t)nxt * 128;
            for (int i = t; i < 4096; i += 256) {
                int r = i >> 5, c4 = i & 31;
                xs4[r * 33 + c4] = xg4[((sb + r) << 5) + c4];
            }
            for (int i = t; i < 2048; i += 256) {
                int r = i >> 4, c4 = i & 15;
                us4[r * 17 + c4] = ug4[((sb + r) << 4) + c4];
            }
        }
        __syncthreads();                  // staging visible before next convert
        prev = tile;
        prevbuf = buf;
        buf ^= 1;
    }
    if (prev >= 0) {
        MBARRIER_WAIT_PARITY(mb, parity); parity ^= 1;
        TCGEN05_FENCE_AFTER();
        uint32_t pd = tb + 192u + (uint32_t)prevbuf * 160u;
        size_t srow = (size_t)prev * 128 + row;
        uint32_t r[32];
        if (hiGrp) {
#pragma unroll
            for (int g = 0; g < 3; g++) {
                TCGEN05_LD_X32(r, pd + g * 32);
                TCGEN05_WAIT_LD();
                float4* dst = (float4*)&dx[srow * 128 + g * 32];
#pragma unroll
                for (int q = 0; q < 8; q++)
                    dst[q] = make_float4(__uint_as_float(r[4 * q]), __uint_as_float(r[4 * q + 1]),
                                         __uint_as_float(r[4 * q + 2]), __uint_as_float(r[4 * q + 3]));
            }
        } else {
            TCGEN05_LD_X32(r, pd + 96);
            TCGEN05_WAIT_LD();
            float4* dst = (float4*)&dx[srow * 128 + 96];
#pragma unroll
            for (int q = 0; q < 8; q++)
                dst[q] = make_float4(__uint_as_float(r[4 * q]), __uint_as_float(r[4 * q + 1]),
                                     __uint_as_float(r[4 * q + 2]), __uint_as_float(r[4 * q + 3]));
            TCGEN05_LD_X32(r, pd + 128);
            TCGEN05_WAIT_LD();
            float4* dy = (float4*)&y[srow * 32];
#pragma unroll
            for (int q = 0; q < 8; q++)
                dy[q] = make_float4(__uint_as_float(r[4 * q]), __uint_as_float(r[4 * q + 1]),
                                    __uint_as_float(r[4 * q + 2]), __uint_as_float(r[4 * q + 3]));
        }
        TCGEN05_FENCE_BEFORE();
    }
    __syncthreads();
    if (t < 32) TCGEN05_DEALLOC(tb, 512);
#else
    // Generic-PTX fallback (never executed on GB300).
    int t = threadIdx.x;
    for (int tile = blockIdx.x; tile < ntiles; tile += gridDim.x) {
        for (int rr = t; rr < 128; rr += blockDim.x) {
            size_t s = (size_t)tile * 128 + rr;
            const float* xr = &x[s * 128];
            for (int o = 0; o < 128; o++) {
                float acc = 0.f;
                for (int k = 0; k < 128; k++) acc += xr[k] * g_A[o * 128 + k];
                dx[s * 128 + o] = acc;
            }
            for (int o = 0; o < 32; o++) {
                float acc = 0.f;
                for (int k = 0; k < 128; k++) acc += xr[k] * g_C[o * 128 + k];
                y[s * 32 + o] = acc;
            }
        }
    }
#endif
}

// ---------------- launcher ----------------
extern "C" void kernel_launch(void* const* d_in, const int* in_sizes, int n_in,
                              void* d_out, int out_size) {
    const float* u = (const float*)d_in[0];
    const float* x = (const float*)d_in[1];
    const float* Q = (const float*)d_in[2];
    const float* P = (const float*)d_in[3];
    const float* S = (const float*)d_in[4];
    const float* G = (const float*)d_in[5];
    const float* H = (const float*)d_in[6];
    int N = in_sizes[0] / 64;
    float* dx = (float*)d_out;
    float* y = dx + (size_t)N * 128;

    k_prep1<<<80, 256>>>(Q, S, G, H);
    k_spec<<<1, 64>>>(Q);
    k_init<<<112, 256>>>(P, G, Q);

    int ns_smem = 16384 * sizeof(float);
    cudaFuncSetAttribute(k_ns_fused, cudaFuncAttributeMaxDynamicSharedMemorySize, ns_smem);
    k_ns_fused<<<NSGRID, 256, ns_smem>>>();

    k_packW<<<120, 256>>>(H);

    int smem = 1024 + W_IMG_BYTES + (XS_F4 + US_F4) * 16;
    cudaFuncSetAttribute(k_main, cudaFuncAttributeMaxDynamicSharedMemorySize, smem);
    int ntiles = N / 128;
    k_main<<<152, 256, smem>>>(x, u, dx, y, ntiles);
}

// round 9
// speedup vs baseline: 8.0090x; 1.1865x over previous
#include <cuda_runtime.h>
#include <cuda_bf16.h>
#include <math.h>
#include <stdint.h>

#define NS_ITERS 16
#define LAN_M 56
#define EPSc 1e-4f
#define IDESC_MAIN 0x8280490u   // f32 accum, bf16 a/b, M=128, N=160
#define W_IMG_HALF 61440
#define W_IMG_BYTES 122880
#define XS_F4 (128 * 33)
#define US_F4 (128 * 17)

#if !defined(__CUDA_ARCH__) || defined(__CUDA_ARCH_FEAT_SM103_ALL) || defined(__CUDA_ARCH_FEAT_SM100_ALL)
#define TC_OK 1
#else
#define TC_OK 0
#endif

// ---------------- PTX helpers ----------------
__device__ __forceinline__ uint32_t smem_u32(const void* p) {
    uint32_t a;
    asm("{ .reg .u64 t; cvta.to.shared.u64 t, %1; cvt.u32.u64 %0, t; }" : "=r"(a) : "l"(p));
    return a;
}
__device__ __forceinline__ uint32_t elect_one_pred() {
    uint32_t pred;
    asm volatile("{\n\t.reg .pred p;\n\telect.sync _|p, 0xFFFFFFFF;\n\tselp.b32 %0, 1, 0, p;\n\t}" : "=r"(pred));
    return pred;
}
#define TCGEN05_ALLOC(a, n) asm volatile("tcgen05.alloc.cta_group::1.sync.aligned.shared::cta.b32 [%0], %1;" :: "r"((uint32_t)(a)), "r"((uint32_t)(n)) : "memory")
#define TCGEN05_DEALLOC(a, n) asm volatile("tcgen05.dealloc.cta_group::1.sync.aligned.b32 %0, %1;" :: "r"(a), "r"((uint32_t)(n)))
#define TCGEN05_RELINQ() asm volatile("tcgen05.relinquish_alloc_permit.cta_group::1.sync.aligned;")
#define TCGEN05_WAIT_ST() asm volatile("tcgen05.wait::st.sync.aligned;" ::: "memory")
#define TCGEN05_WAIT_LD() asm volatile("tcgen05.wait::ld.sync.aligned;" ::: "memory")
#define TCGEN05_FENCE_BEFORE() asm volatile("tcgen05.fence::before_thread_sync;" ::: "memory")
#define TCGEN05_FENCE_AFTER()  asm volatile("tcgen05.fence::after_thread_sync;" ::: "memory")
#define TCGEN05_COMMIT(m) asm volatile("tcgen05.commit.cta_group::1.mbarrier::arrive::one.shared::cluster.b64 [%0];" :: "r"((uint32_t)(m)) : "memory")
#define MBARRIER_INIT(m, c) asm volatile("mbarrier.init.shared.b64 [%0], %1;" :: "r"((uint32_t)(m)), "r"((uint32_t)(c)) : "memory")
#define MBARRIER_WAIT_PARITY(m, ph) do { \
    uint32_t _m = (uint32_t)(m), _p = (uint32_t)(ph), _d; \
    asm volatile("{\n\t.reg .pred p;\n\tmbarrier.try_wait.parity.acquire.cta.shared::cta.b64 p, [%1], %2;\n\tselp.b32 %0, 1, 0, p;\n\t}" : "=r"(_d) : "r"(_m), "r"(_p) : "memory"); \
    if (!_d) { asm volatile("{\n\t.reg .pred P1;\n\tWL_%=:\n\tmbarrier.try_wait.parity.acquire.cta.shared::cta.b64 P1, [%0], %1, 0x989680;\n\t@P1 bra.uni WD_%=;\n\tbra.uni WL_%=;\n\tWD_%=:\n\t}" :: "r"(_m), "r"(_p) : "memory"); } \
} while (0)
#define TCGEN05_MMA_F16(d, a, bd, id, en) do { \
    uint32_t _e = (en) ? 1 : 0, _z = 0; \
    asm volatile("{\n\t.reg .pred p;\n\tsetp.ne.u32 p, %6, 0;\n\ttcgen05.mma.cta_group::1.kind::f16 [%0], [%1], %2, %3, {%4, %4, %4, %4}, p;\n\t}" \
        :: "r"(d), "r"(a), "l"(bd), "r"(id), "r"(_z), "r"(_z), "r"(_e) : "memory"); \
} while (0)
#define TCGEN05_ST_X16(a, r) asm volatile("tcgen05.st.sync.aligned.32x32b.x16.b32 [%0], {%1,%2,%3,%4,%5,%6,%7,%8,%9,%10,%11,%12,%13,%14,%15,%16};" \
    :: "r"(a), "r"((r)[0]), "r"((r)[1]), "r"((r)[2]), "r"((r)[3]), "r"((r)[4]), "r"((r)[5]), "r"((r)[6]), "r"((r)[7]), \
       "r"((r)[8]), "r"((r)[9]), "r"((r)[10]), "r"((r)[11]), "r"((r)[12]), "r"((r)[13]), "r"((r)[14]), "r"((r)[15]) : "memory")
#define TCGEN05_LD_X32(r, a) asm volatile("tcgen05.ld.sync.aligned.32x32b.x32.b32 {%0,%1,%2,%3,%4,%5,%6,%7,%8,%9,%10,%11,%12,%13,%14,%15,%16,%17,%18,%19,%20,%21,%22,%23,%24,%25,%26,%27,%28,%29,%30,%31}, [%32];" \
    : "=r"((r)[0]), "=r"((r)[1]), "=r"((r)[2]), "=r"((r)[3]), "=r"((r)[4]), "=r"((r)[5]), "=r"((r)[6]), "=r"((r)[7]), \
      "=r"((r)[8]), "=r"((r)[9]), "=r"((r)[10]), "=r"((r)[11]), "=r"((r)[12]), "=r"((r)[13]), "=r"((r)[14]), "=r"((r)[15]), \
      "=r"((r)[16]), "=r"((r)[17]), "=r"((r)[18]), "=r"((r)[19]), "=r"((r)[20]), "=r"((r)[21]), "=r"((r)[22]), "=r"((r)[23]), \
      "=r"((r)[24]), "=r"((r)[25]), "=r"((r)[26]), "=r"((r)[27]), "=r"((r)[28]), "=r"((r)[29]), "=r"((r)[30]), "=r"((r)[31]) : "r"(a))
static __device__ __forceinline__ uint64_t make_desc(uint32_t addr) {
    return ((uint64_t)2 << 61) | ((uint64_t)1 << 46) | ((uint64_t)64 << 32) | ((uint64_t)1 << 16)
         | ((uint64_t)(addr >> 4) & 0x3FFF);
}

// ---------------- device scratch ----------------
__device__ __align__(16) float g_HtH[64 * 64];
__device__ __align__(16) float g_A0[128 * 128];
__device__ __align__(16) float g_A[128 * 128];
__device__ __align__(16) float g_C[32 * 128];
__device__ __align__(16) float g_Ybuf[2][128 * 128];
__device__ __align__(16) float g_Zbuf[2][128 * 128];
__device__ __align__(16) float g_T[128 * 128];
__device__ float g_scal[4];
__device__ unsigned g_c1, g_c2;
__device__ volatile unsigned g_s1, g_s2;
__device__ __align__(16) unsigned char g_Wimg[W_IMG_BYTES];

// sense-reversing grid barrier: count resets to 0 each use; sense toggles.
// Each launch uses each barrier an EVEN number of times -> state returns to
// zero -> deterministic across graph replays.
__device__ __forceinline__ void sbar(unsigned* cnt, volatile unsigned* sense,
                                     unsigned G, unsigned target) {
    __syncthreads();
    if (threadIdx.x == 0) {
        __threadfence();
        if (atomicAdd(cnt, 1u) == G - 1u) {
            *cnt = 0u;
            __threadfence();
            *sense = target;
        } else {
            while (*sense != target) { }
            __threadfence();
        }
    }
    __syncthreads();
}

// ---------------- fused setup: prep + spectral + NS + packW ----------------
#define SETUP_GRID 65
__global__ void __launch_bounds__(512, 1) k_setup(
    const float* __restrict__ Q, const float* __restrict__ P,
    const float* __restrict__ S, const float* __restrict__ G,
    const float* __restrict__ H) {
    extern __shared__ float dyn[];          // sA[16384] + sZ[16384]
    float* sA = dyn;
    float* sZ = dyn + 16384;
    __shared__ float rowb[2][128];
    __shared__ float red[512];
    __shared__ float l_al[LAN_M], l_be[LAN_M + 1], l_v[64], l_vp[64];
    __shared__ float l_lo, l_hi;
    __shared__ int l_flag[64];
    int b = blockIdx.x, t = threadIdx.x;

    // ===== phase 1a: HtH, A0, ||Q||_F =====
    if (b < 8) {
        int e = b * 512 + t, i = e >> 6, j = e & 63;
        float s = 0.f;
#pragma unroll 8
        for (int k = 0; k < 128; k++) s += H[k * 64 + i] * H[k * 64 + j];
        g_HtH[e] = s;
    } else if (b < 40) {
        int e = (b - 8) * 512 + t, i = e >> 7, j = e & 127;
        float s = 0.f;
#pragma unroll
        for (int k = 0; k < 32; k++) s += G[k * 128 + i] * G[k * 128 + j];
        g_A0[e] = -0.5f * (Q[e] + s + ((i == j) ? EPSc : 0.f)) + S[e];
    } else if (b == 63) {
        float s = 0.f;
        for (int i = t; i < 16384; i += 512) { float q = Q[i]; s += q * q; }
        red[t] = s; __syncthreads();
        for (int o = 256; o > 0; o >>= 1) { if (t < o) red[t] += red[t + o]; __syncthreads(); }
        if (t == 0) { float c = sqrtf(red[0]); g_scal[0] = 1.f / c; g_scal[2] = c; }
    }
    sbar(&g_c1, &g_s1, SETUP_GRID, 1u);

    // ===== phase 1b: A = A0@P, C = G@P, Y0 = Q/c, Z0 = I =====
    if (b < 32) {
        int e = b * 512 + t, i = e >> 7, j = e & 127;
        const float* a0 = &g_A0[i * 128];
        float s = 0.f;
#pragma unroll 8
        for (int k = 0; k < 128; k++) s += __ldcg(a0 + k) * P[k * 128 + j];
        g_A[e] = s;
    } else if (b < 40) {
        int e = (b - 32) * 512 + t, i = e >> 7, j = e & 127;
        float s = 0.f;
#pragma unroll 8
        for (int k = 0; k < 128; k++) s += G[i * 128 + k] * P[k * 128 + j];
        g_C[e] = s;
    } else if (b < 48) {
        float ic = __ldcg(&g_scal[0]);
        int base = (b - 40) * 2048 + t;
#pragma unroll
        for (int r = 0; r < 4; r++) g_Ybuf[0][base + r * 512] = Q[base + r * 512] * ic;
    } else if (b < 56) {
        int base = (b - 48) * 2048 + t;
#pragma unroll
        for (int r = 0; r < 4; r++) { int e = base + r * 512; g_Zbuf[0][e] = ((e >> 7) == (e & 127)) ? 1.f : 0.f; }
    }
    sbar(&g_c1, &g_s1, SETUP_GRID, 0u);

    // ===== phase 2: NS (CTAs 0..63) || Lanczos (CTA 64) =====
    if (b < 64) {
        unsigned s2 = 0;
        int p = 0;
        int half = t >> 8, tt = t & 255;
        int i = tt >> 7, j = tt & 127;
        int r0 = b * 2;
        for (int it = 0; it < NS_ITERS; it++) {
            const float* Y = g_Ybuf[p];
            const float* Z = g_Zbuf[p];
            float* Yn = g_Ybuf[p ^ 1];
            float* Zn = g_Zbuf[p ^ 1];
            // phase A: T = 1.5I - 0.5 Z@Y ; half1 pre-stages Z
            if (half == 0) {
                for (int q = tt; q < 4096; q += 256) ((float4*)sA)[q] = __ldcg(((const float4*)Y) + q);
                rowb[i][j] = __ldcg(&Z[(r0 + i) * 128 + j]);
            } else {
                for (int q = tt; q < 4096; q += 256) ((float4*)sZ)[q] = __ldcg(((const float4*)Z) + q);
            }
            __syncthreads();
            if (half == 0) {
                const float* rw = rowb[i];
                float s = 0.f;
#pragma unroll 8
                for (int k = 0; k < 128; k++) s += rw[k] * sA[k * 128 + j];
                g_T[(r0 + i) * 128 + j] = (((r0 + i) == j) ? 1.5f : 0.f) - 0.5f * s;
            }
            s2 ^= 1; sbar(&g_c2, &g_s2, 64u, s2);
            // phase B: Yn = Y@T (half0), Zn = T@Z (half1); T staged by all
            for (int q = t; q < 4096; q += 512) ((float4*)sA)[q] = __ldcg(((const float4*)g_T) + q);
            if (half == 0) rowb[i][j] = __ldcg(&Y[(r0 + i) * 128 + j]);
            __syncthreads();
            if (half == 0) {
                const float* rw = rowb[i];
                float s = 0.f;
#pragma unroll 8
                for (int k = 0; k < 128; k++) s += rw[k] * sA[k * 128 + j];
                Yn[(r0 + i) * 128 + j] = s;
            } else {
                const float* tr = &sA[(r0 + i) * 128];
                float s = 0.f;
#pragma unroll 8
                for (int k = 0; k < 128; k++) s += tr[k] * sZ[k * 128 + j];
                Zn[(r0 + i) * 128 + j] = s;
            }
            s2 ^= 1; sbar(&g_c2, &g_s2, 64u, s2);
            p ^= 1;
        }
    } else {
        // Lanczos lam_max(HtH) on CTA 64; sM lives in sA
        float* sM = sA;
        for (int q = t; q < 4096; q += 512) sM[q] = __ldcg(&g_HtH[q]);
        __syncthreads();
        if (t < 64) {
            float rs = 0.f;
            for (int k = 0; k < 64; k++) rs += sM[t * 64 + k];
            l_v[t] = rs; red[t] = rs * rs;
        }
        __syncthreads();
        for (int o = 32; o > 0; o >>= 1) { if (t < o) red[t] += red[t + o]; __syncthreads(); }
        if (t < 64) { l_v[t] = l_v[t] / sqrtf(red[0]); l_vp[t] = 0.f; }
        if (t == 0) l_be[0] = 0.f;
        __syncthreads();
        for (int jj = 0; jj < LAN_M; jj++) {
            float wi = 0.f;
            if (t < 64) {
                float acc = 0.f;
#pragma unroll 8
                for (int k = 0; k < 64; k++) acc += sM[t * 64 + k] * l_v[k];
                wi = acc - l_be[jj] * l_vp[t];
                red[t] = wi * l_v[t];
            }
            __syncthreads();
            for (int o = 32; o > 0; o >>= 1) { if (t < o) red[t] += red[t + o]; __syncthreads(); }
            float a = red[0]; __syncthreads();
            if (t == 0) l_al[jj] = a;
            if (t < 64) { wi -= a * l_v[t]; red[t] = wi * wi; }
            __syncthreads();
            for (int o = 32; o > 0; o >>= 1) { if (t < o) red[t] += red[t + o]; __syncthreads(); }
            float bn = sqrtf(red[0]); __syncthreads();
            if (t == 0) l_be[jj + 1] = bn;
            if (t < 64) { l_vp[t] = l_v[t]; l_v[t] = (bn > 1e-12f) ? (wi / bn) : 0.f; }
            __syncthreads();
        }
        if (t == 0) {
            float hi = 0.f;
            for (int jj = 0; jj < LAN_M; jj++) {
                float g = l_al[jj] + fabsf(l_be[jj]) + fabsf(l_be[jj + 1]);
                if (g > hi) hi = g;
            }
            l_lo = 0.f; l_hi = hi + 1.f;
        }
        __syncthreads();
        for (int r = 0; r < 5; r++) {
            float lo = l_lo, hi = l_hi;
            if (t < 64) {
                float xm = lo + (hi - lo) * (float)(t + 1) * (1.f / 65.f);
                int cnt = 0; float d = 1.f;
                for (int jj = 0; jj < LAN_M; jj++) {
                    float bj = (jj == 0) ? 0.f : l_be[jj];
                    d = (l_al[jj] - xm) - __fdividef(bj * bj, d);
                    if (d == 0.f) d = -1e-30f;
                    if (d < 0.f) cnt++;
                }
                l_flag[t] = (cnt >= LAN_M) ? 1 : 0;
            }
            __syncthreads();
            if (t == 0) {
                float nlo = lo, nhi = hi;
                for (int q = 0; q < 64; q++) {
                    float sq = lo + (hi - lo) * (float)(q + 1) * (1.f / 65.f);
                    if (l_flag[q]) { nhi = sq; break; }
                    nlo = sq;
                }
                l_lo = nlo; l_hi = nhi;
            }
            __syncthreads();
        }
        if (t == 0) {
            float lam = 0.5f * (l_lo + l_hi);
            if (lam < 1e-20f) lam = 1e-20f;
            float cfro = __ldcg(&g_scal[2]);
            g_scal[1] = sqrtf(cfro) / (1.01f * sqrtf(lam));
        }
    }
    sbar(&g_c1, &g_s1, SETUP_GRID, 1u);

    // ===== phase 3: packW (B computed inline) =====
    {
        int idx = b * 512 + t;
        if (idx < 30720) {
            int o = idx / 192, k = idx % 192;
            float v;
            if (k < 128) {
                v = (o < 128) ? __ldcg(&g_A[o * 128 + k]) : __ldcg(&g_C[(o - 128) * 128 + k]);
            } else if (o < 128) {
                const float* yr = &g_Ybuf[0][o * 128];
                int j = k - 128;
                float s = 0.f;
#pragma unroll 8
                for (int kk = 0; kk < 128; kk++) s += __ldcg(yr + kk) * H[kk * 64 + j];
                v = s * __ldcg(&g_scal[1]);
            } else {
                v = 0.f;
            }
            __nv_bfloat16 h = __float2bfloat16_rn(v);
            __nv_bfloat16 l = __float2bfloat16_rn(v - __bfloat162float(h));
            uint32_t boff = (uint32_t)(((o >> 3) + (k >> 6) * 20) * 1024 + (o & 7) * 128 + (k & 63) * 2);
            uint32_t sw = boff ^ ((boff >> 3) & 0x70);
            *(unsigned short*)(g_Wimg + sw) = __bfloat16_as_ushort(h);
            *(unsigned short*)(g_Wimg + W_IMG_HALF + sw) = __bfloat16_as_ushort(l);
        }
    }
    sbar(&g_c1, &g_s1, SETUP_GRID, 0u);
}

// ---------------- main GEMM: tcgen05 bf16 split (identical to R8) ----------------
__device__ __forceinline__ uint32_t packhi2(float a, float b) {
    __nv_bfloat16 ha = __float2bfloat16_rn(a), hb = __float2bfloat16_rn(b);
    return (uint32_t)__bfloat16_as_ushort(ha) | ((uint32_t)__bfloat16_as_ushort(hb) << 16);
}
__device__ __forceinline__ uint32_t packlo2(float a, float b) {
    __nv_bfloat16 ha = __float2bfloat16_rn(a), hb = __float2bfloat16_rn(b);
    float ra = a - __bfloat162float(ha), rb = b - __bfloat162float(hb);
    __nv_bfloat16 la = __float2bfloat16_rn(ra), lb = __float2bfloat16_rn(rb);
    return (uint32_t)__bfloat16_as_ushort(la) | ((uint32_t)__bfloat16_as_ushort(lb) << 16);
}

__global__ void __launch_bounds__(256, 1) k_main(
    const float* __restrict__ x, const float* __restrict__ u,
    float* __restrict__ dx, float* __restrict__ y, int ntiles) {
#if TC_OK
    extern __shared__ unsigned char smraw[];
    __shared__ uint32_t s_tptr;
    __shared__ __align__(8) unsigned long long s_mbar;
    int t = threadIdx.x;
    int wid = t >> 5;
    int sub = wid & 3;
    int lane = t & 31;
    int row = sub * 32 + lane;
    bool hiGrp = wid < 4;
    uint32_t smbase = smem_u32(smraw);
    uint32_t wbase = (smbase + 1023u) & ~1023u;
    unsigned char* wptr = smraw + (wbase - smbase);
    float4* xs4 = (float4*)(wptr + W_IMG_BYTES);
    float4* us4 = xs4 + XS_F4;
    {
        const float4* src = (const float4*)g_Wimg;
        float4* dst = (float4*)wptr;
        for (int i = t; i < W_IMG_BYTES / 16; i += 256) dst[i] = src[i];
    }
    if (t < 32) { TCGEN05_ALLOC(smem_u32(&s_tptr), 512); TCGEN05_RELINQ(); }
    if (t == 0) MBARRIER_INIT(smem_u32(&s_mbar), 1);
    __syncthreads();
    uint32_t tb = s_tptr;
    uint32_t mb = smem_u32(&s_mbar);
    uint64_t descH = make_desc(wbase);
    uint64_t descL = make_desc(wbase + W_IMG_HALF);
    uint32_t wofs = (uint32_t)sub << 21;
    uint32_t parity = 0;
    int prev = -1;
    int buf = 0, prevbuf = 0;
    const float4* xg4 = (const float4*)x;
    const float4* ug4 = (const float4*)u;

    if (blockIdx.x < ntiles) {
        size_t sb = (size_t)blockIdx.x * 128;
        for (int i = t; i < 4096; i += 256) {
            int r = i >> 5, c4 = i & 31;
            xs4[r * 33 + c4] = xg4[((sb + r) << 5) + c4];
        }
        for (int i = t; i < 2048; i += 256) {
            int r = i >> 4, c4 = i & 15;
            us4[r * 17 + c4] = ug4[((sb + r) << 4) + c4];
        }
    }
    __syncthreads();

    for (int tile = blockIdx.x; tile < ntiles; tile += gridDim.x) {
        if (prev >= 0) { MBARRIER_WAIT_PARITY(mb, parity); parity ^= 1; TCGEN05_FENCE_AFTER(); }
        const float4* xr4 = xs4 + row * 33;
        const float4* ur4 = us4 + row * 17;
#pragma unroll
        for (int c = 0; c < 6; c++) {
            float4 v[8];
#pragma unroll
            for (int q = 0; q < 8; q++) v[q] = (c < 4) ? xr4[c * 8 + q] : ur4[(c - 4) * 8 + q];
            uint32_t pk[16];
            if (hiGrp) {
#pragma unroll
                for (int q = 0; q < 8; q++) {
                    pk[2 * q]     = packhi2(v[q].x, v[q].y);
                    pk[2 * q + 1] = packhi2(v[q].z, v[q].w);
                }
                TCGEN05_ST_X16(tb + (uint32_t)(c * 16) + wofs, pk);
            } else {
#pragma unroll
                for (int q = 0; q < 8; q++) {
                    pk[2 * q]     = packlo2(v[q].x, v[q].y);
                    pk[2 * q + 1] = packlo2(v[q].z, v[q].w);
                }
                TCGEN05_ST_X16(tb + (uint32_t)(96 + c * 16) + wofs, pk);
            }
        }
        TCGEN05_WAIT_ST();
        TCGEN05_FENCE_BEFORE();
        __syncthreads();
        uint32_t dcol = tb + 192u + (uint32_t)buf * 160u;
        if (t < 32) {
            TCGEN05_FENCE_AFTER();
            if (elect_one_pred()) {
                int idx = 0;
#pragma unroll
                for (int term = 0; term < 3; term++) {
                    uint32_t ab = tb + ((term == 2) ? 96u : 0u);
                    uint64_t bd = (term == 1) ? descL : descH;
#pragma unroll
                    for (int k = 0; k < 12; k++) {
                        uint64_t d = bd + (uint64_t)((k >> 2) * 1280 + (k & 3) * 2);
                        TCGEN05_MMA_F16(dcol, ab + (uint32_t)(k * 8), d, IDESC_MAIN, idx > 0);
                        idx++;
                    }
                }
                TCGEN05_COMMIT(mb);
            }
        }
        if (prev >= 0) {
            uint32_t pd = tb + 192u + (uint32_t)prevbuf * 160u;
            size_t srow = (size_t)prev * 128 + row;
            uint32_t r[32];
            if (hiGrp) {
#pragma unroll
                for (int g = 0; g < 3; g++) {
                    TCGEN05_LD_X32(r, pd + g * 32);
                    TCGEN05_WAIT_LD();
                    float4* dst = (float4*)&dx[srow * 128 + g * 32];
#pragma unroll
                    for (int q = 0; q < 8; q++)
                        dst[q] = make_float4(__uint_as_float(r[4 * q]), __uint_as_float(r[4 * q + 1]),
                                             __uint_as_float(r[4 * q + 2]), __uint_as_float(r[4 * q + 3]));
                }
            } else {
                TCGEN05_LD_X32(r, pd + 96);
                TCGEN05_WAIT_LD();
                float4* dst = (float4*)&dx[srow * 128 + 96];
#pragma unroll
                for (int q = 0; q < 8; q++)
                    dst[q] = make_float4(__uint_as_float(r[4 * q]), __uint_as_float(r[4 * q + 1]),
                                         __uint_as_float(r[4 * q + 2]), __uint_as_float(r[4 * q + 3]));
                TCGEN05_LD_X32(r, pd + 128);
                TCGEN05_WAIT_LD();
                float4* dy = (float4*)&y[srow * 32];
#pragma unroll
                for (int q = 0; q < 8; q++)
                    dy[q] = make_float4(__uint_as_float(r[4 * q]), __uint_as_float(r[4 * q + 1]),
                                        __uint_as_float(r[4 * q + 2]), __uint_as_float(r[4 * q + 3]));
            }
            TCGEN05_FENCE_BEFORE();
        }
        int nxt = tile + gridDim.x;
        if (nxt < ntiles) {
            size_t sb = (size_t)nxt * 128;
            for (int i = t; i < 4096; i += 256) {
                int r = i >> 5, c4 = i & 31;
                xs4[r * 33 + c4] = xg4[((sb + r) << 5) + c4];
            }
            for (int i = t; i < 2048; i += 256) {
                int r = i >> 4, c4 = i & 15;
                us4[r * 17 + c4] = ug4[((sb + r) << 4) + c4];
            }
        }
        __syncthreads();
        prev = tile;
        prevbuf = buf;
        buf ^= 1;
    }
    if (prev >= 0) {
        MBARRIER_WAIT_PARITY(mb, parity); parity ^= 1;
        TCGEN05_FENCE_AFTER();
        uint32_t pd = tb + 192u + (uint32_t)prevbuf * 160u;
        size_t srow = (size_t)prev * 128 + row;
        uint32_t r[32];
        if (hiGrp) {
#pragma unroll
            for (int g = 0; g < 3; g++) {
                TCGEN05_LD_X32(r, pd + g * 32);
                TCGEN05_WAIT_LD();
                float4* dst = (float4*)&dx[srow * 128 + g * 32];
#pragma unroll
                for (int q = 0; q < 8; q++)
                    dst[q] = make_float4(__uint_as_float(r[4 * q]), __uint_as_float(r[4 * q + 1]),
                                         __uint_as_float(r[4 * q + 2]), __uint_as_float(r[4 * q + 3]));
            }
        } else {
            TCGEN05_LD_X32(r, pd + 96);
            TCGEN05_WAIT_LD();
            float4* dst = (float4*)&dx[srow * 128 + 96];
#pragma unroll
            for (int q = 0; q < 8; q++)
                dst[q] = make_float4(__uint_as_float(r[4 * q]), __uint_as_float(r[4 * q + 1]),
                                     __uint_as_float(r[4 * q + 2]), __uint_as_float(r[4 * q + 3]));
            TCGEN05_LD_X32(r, pd + 128);
            TCGEN05_WAIT_LD();
            float4* dy = (float4*)&y[srow * 32];
#pragma unroll
            for (int q = 0; q < 8; q++)
                dy[q] = make_float4(__uint_as_float(r[4 * q]), __uint_as_float(r[4 * q + 1]),
                                    __uint_as_float(r[4 * q + 2]), __uint_as_float(r[4 * q + 3]));
        }
        TCGEN05_FENCE_BEFORE();
    }
    __syncthreads();
    if (t < 32) TCGEN05_DEALLOC(tb, 512);
#else
    // Generic-PTX fallback (never executed on GB300).
    int t = threadIdx.x;
    for (int tile = blockIdx.x; tile < ntiles; tile += gridDim.x) {
        for (int rr = t; rr < 128; rr += blockDim.x) {
            size_t s = (size_t)tile * 128 + rr;
            const float* xr = &x[s * 128];
            for (int o = 0; o < 128; o++) {
                float acc = 0.f;
                for (int k = 0; k < 128; k++) acc += xr[k] * g_A[o * 128 + k];
                dx[s * 128 + o] = acc;
            }
            for (int o = 0; o < 32; o++) {
                float acc = 0.f;
                for (int k = 0; k < 128; k++) acc += xr[k] * g_C[o * 128 + k];
                y[s * 32 + o] = acc;
            }
        }
    }
#endif
}

// ---------------- launcher (2 launches per call) ----------------
extern "C" void kernel_launch(void* const* d_in, const int* in_sizes, int n_in,
                              void* d_out, int out_size) {
    const float* u = (const float*)d_in[0];
    const float* x = (const float*)d_in[1];
    const float* Q = (const float*)d_in[2];
    const float* P = (const float*)d_in[3];
    const float* S = (const float*)d_in[4];
    const float* G = (const float*)d_in[5];
    const float* H = (const float*)d_in[6];
    int N = in_sizes[0] / 64;
    float* dx = (float*)d_out;
    float* y = dx + (size_t)N * 128;

    int setup_smem = 32768 * sizeof(float);   // 128 KB
    cudaFuncSetAttribute(k_setup, cudaFuncAttributeMaxDynamicSharedMemorySize, setup_smem);
    k_setup<<<SETUP_GRID, 512, setup_smem>>>(Q, P, S, G, H);

    int smem = 1024 + W_IMG_BYTES + (XS_F4 + US_F4) * 16;
    cudaFuncSetAttribute(k_main, cudaFuncAttributeMaxDynamicSharedMemorySize, smem);
    int ntiles = N / 128;
    k_main<<<152, 256, smem>>>(x, u, dx, y, ntiles);
}